// round 14
// baseline (speedup 1.0000x reference)
#include <cuda_runtime.h>
#include <cuda_fp16.h>
#include <math.h>
#include <stdint.h>

// Problem constants
#define Vv    32000
#define Ee    512
#define Hh    512
#define Tt    128
#define Bb    4
#define Dd    4
#define Ll    2
#define C0c   2000
#define C1c   10000
#define NTt   125            // T - D + 1
#define NROW  2000           // B*NT*D
#define NDEC  500            // B*NT
#define NENC  512            // B*T
#define G3H   1536           // 3*H
#define HLDC  2004           // padded head-logit row stride
#define W0    8000           // C1-C0
#define W1    22000          // V-C1

// partial-LSE strides
#define PH    64
#define P0    252
#define P1    688

// STORE modes
#define ST_F32   0
#define ST_F16   1
#define ST_NONE  2
#define ST_OUTS  3   // staged, coalesced direct-to-out store with correction+mask

// ---------------- device scratch ----------------
// hs layout: [d][NDEC][H] (step-major). Output row R = bt*4+d -> scratch row sr = d*NDEC+bt.
__device__ float g_embedded[NENC * Ee];
__device__ float g_inputf[NENC * Ee];
__device__ float g_wgt[NENC * Ee];
__device__ float g_egi[NENC * G3H];
__device__ float g_gi[NROW * G3H];
__device__ float g_gh[NENC * G3H];
__device__ float g_wins[Dd * NDEC * Ee];
__device__ float g_h[NDEC * Hh];
__device__ float g_hs[NROW * Hh];
__device__ float g_z0[NROW * 128];
__device__ float g_z1[NROW * 32];
__device__ __half g_headlog[NROW * HLDC];
__device__ float g_lseh[NROW];
__device__ float g_lse0[NROW];
__device__ float g_lse1[NROW];
__device__ float2 g_parth[NROW * PH];
__device__ float2 g_part0[NROW * P0];
__device__ float2 g_part1[NROW * P1];

// ---------------- tf32 helpers ----------------
__device__ __forceinline__ uint32_t f2tf(float f) {
    uint32_t u;
    asm("cvt.rna.tf32.f32 %0, %1;" : "=r"(u) : "f"(f));
    return u;
}

__device__ __forceinline__ void mma_tf32(float* d, const uint32_t* a, const uint32_t* b) {
    asm volatile(
        "mma.sync.aligned.m16n8k8.row.col.f32.tf32.tf32.f32 "
        "{%0,%1,%2,%3}, {%4,%5,%6,%7}, {%8,%9}, {%0,%1,%2,%3};"
        : "+f"(d[0]), "+f"(d[1]), "+f"(d[2]), "+f"(d[3])
        : "r"(a[0]), "r"(a[1]), "r"(a[2]), "r"(a[3]), "r"(b[0]), "r"(b[1]));
}

__device__ __forceinline__ void lse_merge(float& m, float& s, float om, float os) {
    float M = fmaxf(m, om);
    s = s * expf(m - M) + os * expf(om - M);
    m = M;
}

__device__ __forceinline__ float sigmf(float v) { return 1.f / (1.f + expf(-v)); }

// ---------------- generic tf32 GEMM: C[M,N] = A[M,K] * B[N,K]^T ----------------
// ST_OUTS (BM=128 only): stage C tile as fp16 in smem, then coalesced masked
// float4 stores into out rows R=bt*4+d (sr = d*NDEC+bt), with c = hl[headcol]-lseh-lse2.
template <int BM, bool DUAL, bool FUSE_LSE, int STORE>
__global__ void __launch_bounds__(256)
k_tf32_gemm(const float* __restrict__ A0, const float* __restrict__ B0, void* __restrict__ C0p,
            const float* __restrict__ A1, const float* __restrict__ B1, void* __restrict__ C1p,
            int M, int N, int K, int ldc, float2* __restrict__ part, int pstride,
            int colStart, const __half* __restrict__ hlp, int headcol,
            const float* __restrict__ lseh, const float* __restrict__ lse2,
            const int* __restrict__ lengths) {
    const float* A = (DUAL && blockIdx.z) ? A1 : A0;
    const float* B = (DUAL && blockIdx.z) ? B1 : B0;
    void*      Cp = (DUAL && blockIdx.z) ? C1p : C0p;

    constexpr int MF = BM / 32;
    constexpr int PA = BM / 32;
    __shared__ uint32_t Smem[(BM + 128) * 32];
    uint32_t* As = Smem;
    uint32_t* Bs = Smem + BM * 32;

    int tid = threadIdx.x;
    int lane = tid & 31, wid = tid >> 5;
    int tig = lane & 3, grp4 = lane >> 2;
    int wm = (wid & 1) * (BM / 2);
    int wn = (wid >> 1) * 32;
    int m0 = blockIdx.y * BM, n0 = blockIdx.x * 128;

    float acc[MF][4][4];
#pragma unroll
    for (int i = 0; i < MF; i++)
#pragma unroll
        for (int j = 0; j < 4; j++)
#pragma unroll
            for (int k = 0; k < 4; k++) acc[i][j][k] = 0.f;

    int aRow[PA], aGrp[PA], aOk[PA];
    const float* aPtr[PA];
    int bRow[4], bGrp[4], bOk[4];
    const float* bPtr[4];
#pragma unroll
    for (int p = 0; p < PA; p++) {
        int idx = tid + p * 256;
        aRow[p] = idx >> 3; aGrp[p] = idx & 7;
        int gm = m0 + aRow[p];
        aOk[p] = (gm < M);
        aPtr[p] = A + (size_t)(aOk[p] ? gm : 0) * K + aGrp[p] * 4;
    }
#pragma unroll
    for (int p = 0; p < 4; p++) {
        int idx = tid + p * 256;
        bRow[p] = idx >> 3; bGrp[p] = idx & 7;
        int gn = n0 + bRow[p];
        bOk[p] = (gn < N);
        bPtr[p] = B + (size_t)(bOk[p] ? gn : 0) * K + bGrp[p] * 4;
    }

    const float4 z4 = make_float4(0.f, 0.f, 0.f, 0.f);
    float4 pa[PA], pb[4];
#pragma unroll
    for (int p = 0; p < PA; p++) pa[p] = aOk[p] ? *(const float4*)(aPtr[p]) : z4;
#pragma unroll
    for (int p = 0; p < 4; p++)  pb[p] = bOk[p] ? *(const float4*)(bPtr[p]) : z4;

    int nk = K >> 5;
    for (int ks = 0; ks < nk; ks++) {
#pragma unroll
        for (int p = 0; p < PA; p++) {
            uint32_t* d = &As[aRow[p] * 32 + ((aGrp[p] ^ (aRow[p] & 7)) << 2)];
            *(uint4*)d = make_uint4(f2tf(pa[p].x), f2tf(pa[p].y), f2tf(pa[p].z), f2tf(pa[p].w));
        }
#pragma unroll
        for (int p = 0; p < 4; p++) {
            uint32_t* d = &Bs[bRow[p] * 32 + ((bGrp[p] ^ (bRow[p] & 7)) << 2)];
            *(uint4*)d = make_uint4(f2tf(pb[p].x), f2tf(pb[p].y), f2tf(pb[p].z), f2tf(pb[p].w));
        }
        __syncthreads();

        if (ks + 1 < nk) {
            int off = (ks + 1) * 32;
#pragma unroll
            for (int p = 0; p < PA; p++) pa[p] = aOk[p] ? *(const float4*)(aPtr[p] + off) : z4;
#pragma unroll
            for (int p = 0; p < 4; p++)  pb[p] = bOk[p] ? *(const float4*)(bPtr[p] + off) : z4;
        }

#pragma unroll
        for (int kk = 0; kk < 4; kk++) {
            int g0 = kk * 2, g1 = kk * 2 + 1;
            uint32_t a[MF][4], b[4][2];
#pragma unroll
            for (int mf = 0; mf < MF; mf++) {
                int r = wm + mf * 16 + grp4;
                int base = r * 32 + tig;
                int s0 = (g0 ^ (r & 7)) << 2;
                int s1 = (g1 ^ (r & 7)) << 2;
                a[mf][0] = As[base + s0];
                a[mf][1] = As[base + 256 + s0];
                a[mf][2] = As[base + s1];
                a[mf][3] = As[base + 256 + s1];
            }
#pragma unroll
            for (int nf = 0; nf < 4; nf++) {
                int rn = wn + nf * 8 + grp4;
                int base = rn * 32 + tig;
                b[nf][0] = Bs[base + ((g0 ^ (rn & 7)) << 2)];
                b[nf][1] = Bs[base + ((g1 ^ (rn & 7)) << 2)];
            }
#pragma unroll
            for (int mf = 0; mf < MF; mf++)
#pragma unroll
                for (int nf = 0; nf < 4; nf++)
                    mma_tf32(acc[mf][nf], a[mf], b[nf]);
        }
        __syncthreads();
    }

    if (STORE == ST_F32 || STORE == ST_F16) {
#pragma unroll
        for (int mf = 0; mf < MF; mf++) {
            int r0 = m0 + wm + mf * 16 + grp4;
            int r1 = r0 + 8;
#pragma unroll
            for (int nf = 0; nf < 4; nf++) {
                int cb = n0 + wn + nf * 8 + 2 * tig;
                if (cb >= N) continue;
                if (STORE == ST_F16) {
                    __half* C = (__half*)Cp;
                    if (r0 < M) *(__half2*)(C + (size_t)r0 * ldc + cb) =
                        __floats2half2_rn(acc[mf][nf][0], acc[mf][nf][1]);
                    if (r1 < M) *(__half2*)(C + (size_t)r1 * ldc + cb) =
                        __floats2half2_rn(acc[mf][nf][2], acc[mf][nf][3]);
                } else {
                    float* C = (float*)Cp;
                    if (r0 < M) *(float2*)(C + (size_t)r0 * ldc + cb) = make_float2(acc[mf][nf][0], acc[mf][nf][1]);
                    if (r1 < M) *(float2*)(C + (size_t)r1 * ldc + cb) = make_float2(acc[mf][nf][2], acc[mf][nf][3]);
                }
            }
        }
    }

    if (FUSE_LSE) {
        int xc = blockIdx.x * 4 + (wid >> 1);
#pragma unroll
        for (int mf = 0; mf < MF; mf++) {
#pragma unroll
            for (int half = 0; half < 2; half++) {
                int row = m0 + wm + mf * 16 + grp4 + half * 8;
                float mx = -1e30f;
#pragma unroll
                for (int nf = 0; nf < 4; nf++) {
                    int cb = n0 + wn + nf * 8 + 2 * tig;
                    if (cb < N)     mx = fmaxf(mx, acc[mf][nf][half * 2]);
                    if (cb + 1 < N) mx = fmaxf(mx, acc[mf][nf][half * 2 + 1]);
                }
                mx = fmaxf(mx, __shfl_xor_sync(0xffffffffu, mx, 1));
                mx = fmaxf(mx, __shfl_xor_sync(0xffffffffu, mx, 2));
                float s = 0.f;
#pragma unroll
                for (int nf = 0; nf < 4; nf++) {
                    int cb = n0 + wn + nf * 8 + 2 * tig;
                    if (cb < N)     s += expf(acc[mf][nf][half * 2]     - mx);
                    if (cb + 1 < N) s += expf(acc[mf][nf][half * 2 + 1] - mx);
                }
                s += __shfl_xor_sync(0xffffffffu, s, 1);
                s += __shfl_xor_sync(0xffffffffu, s, 2);
                if (tig == 0 && row < M)
                    part[(size_t)row * pstride + xc] = make_float2(mx, s);
            }
        }
    }

    if (STORE == ST_OUTS) {
        // stage tile as fp16 in smem (reuses As/Bs space; 128x128 fp16 = 32 KB)
        __half* stage = (__half*)Smem;
#pragma unroll
        for (int mf = 0; mf < MF; mf++) {
            int lr0 = wm + mf * 16 + grp4;
            int lr1 = lr0 + 8;
#pragma unroll
            for (int nf = 0; nf < 4; nf++) {
                int lc = wn + nf * 8 + 2 * tig;
                *(__half2*)(stage + lr0 * 128 + lc) = __floats2half2_rn(acc[mf][nf][0], acc[mf][nf][1]);
                *(__half2*)(stage + lr1 * 128 + lc) = __floats2half2_rn(acc[mf][nf][2], acc[mf][nf][3]);
            }
        }
        __syncthreads();
        float* outp = (float*)Cp;
#pragma unroll 1
        for (int rr = 0; rr < BM / 8; rr++) {
            int lr = wid * (BM / 8) + rr;
            int sr = m0 + lr;
            if (sr >= M) continue;
            int dd = sr / NDEC;
            int bt = sr - dd * NDEC;
            int b = bt / NTt, t = bt - b * NTt;
            int R = bt * 4 + dd;
            int gc = n0 + lane * 4;
            if (gc >= N) continue;
            float4 w;
            if (t < __ldg(lengths + b)) {
                float c = __half2float(__ldg(hlp + (size_t)sr * HLDC + headcol))
                          - __ldg(lseh + sr) - __ldg(lse2 + sr);
                __half2 h01 = *(__half2*)(stage + lr * 128 + lane * 4);
                __half2 h23 = *(__half2*)(stage + lr * 128 + lane * 4 + 2);
                float2 f01 = __half22float2(h01);
                float2 f23 = __half22float2(h23);
                w = make_float4(f01.x + c, f01.y + c, f23.x + c, f23.y + c);
            } else {
                w = make_float4(0.f, 0.f, 0.f, 0.f);
            }
            __stcs((float4*)(outp + (size_t)R * Vv + colStart + gc), w);
        }
    }
}

// ---------------- tf32 einsum, small tiles for full-chip occupancy ----------------
__global__ void __launch_bounds__(256)
k_gt_tf32(const float* __restrict__ G, int l, const float* __restrict__ X, float* __restrict__ C) {
    int b  = blockIdx.z;
    int i0 = blockIdx.y * 32;
    int d0 = blockIdx.x * 64;
    const float* Gb = G + ((size_t)b * Ll + l) * Tt * Tt;
    const float* Xb = X + (size_t)b * Tt * Ee;

    __shared__ uint32_t As[32 * 32];
    __shared__ uint32_t Bs[64 * 32];

    int tid = threadIdx.x;
    int lane = tid & 31, wid = tid >> 5;
    int tig = lane & 3, grp4 = lane >> 2;
    int wm = (wid & 1) * 16;
    int wn = (wid >> 1) * 16;

    float acc[2][4];
#pragma unroll
    for (int j = 0; j < 2; j++)
#pragma unroll
        for (int k = 0; k < 4; k++) acc[j][k] = 0.f;

    int jlA = tid & 31, i4A = tid >> 5;
    int jlB[2], d4B[2];
#pragma unroll
    for (int p = 0; p < 2; p++) { int idx = tid + p * 256; jlB[p] = idx & 31; d4B[p] = idx >> 5; }

    float4 ga, xa[2];
    ga = *(const float4*)(Gb + (size_t)jlA * Tt + i0 + i4A * 4);
#pragma unroll
    for (int p = 0; p < 2; p++) xa[p] = *(const float4*)(Xb + (size_t)jlB[p] * Ee + d0 + d4B[p] * 4);

    for (int ks = 0; ks < 4; ks++) {
        {
            int grp = jlA >> 2, t = jlA & 3;
            float gv[4] = {ga.x, ga.y, ga.z, ga.w};
#pragma unroll
            for (int q = 0; q < 4; q++) {
                int r = i4A * 4 + q;
                As[r * 32 + ((grp ^ (r & 7)) << 2) + t] = f2tf(gv[q]);
            }
        }
#pragma unroll
        for (int p = 0; p < 2; p++) {
            int grp = jlB[p] >> 2, t = jlB[p] & 3;
            float xf[4] = {xa[p].x, xa[p].y, xa[p].z, xa[p].w};
#pragma unroll
            for (int q = 0; q < 4; q++) {
                int r = d4B[p] * 4 + q;
                Bs[r * 32 + ((grp ^ (r & 7)) << 2) + t] = f2tf(xf[q]);
            }
        }
        __syncthreads();

        if (ks < 3) {
            int j0 = (ks + 1) * 32;
            ga = *(const float4*)(Gb + (size_t)(j0 + jlA) * Tt + i0 + i4A * 4);
#pragma unroll
            for (int p = 0; p < 2; p++) xa[p] = *(const float4*)(Xb + (size_t)(j0 + jlB[p]) * Ee + d0 + d4B[p] * 4);
        }

#pragma unroll
        for (int kk = 0; kk < 4; kk++) {
            int g0 = kk * 2, g1 = kk * 2 + 1;
            uint32_t a[4], bb[2][2];
            {
                int r = wm + grp4;
                int base = r * 32 + tig;
                int s0 = (g0 ^ (r & 7)) << 2;
                int s1 = (g1 ^ (r & 7)) << 2;
                a[0] = As[base + s0];
                a[1] = As[base + 256 + s0];
                a[2] = As[base + s1];
                a[3] = As[base + 256 + s1];
            }
#pragma unroll
            for (int nf = 0; nf < 2; nf++) {
                int rn = wn + nf * 8 + grp4;
                int base = rn * 32 + tig;
                bb[nf][0] = Bs[base + ((g0 ^ (rn & 7)) << 2)];
                bb[nf][1] = Bs[base + ((g1 ^ (rn & 7)) << 2)];
            }
#pragma unroll
            for (int nf = 0; nf < 2; nf++)
                mma_tf32(acc[nf], a, bb[nf]);
        }
        __syncthreads();
    }

    float* Cb = C + (size_t)b * Tt * Ee;
    int r0 = i0 + wm + grp4;
    int r1 = r0 + 8;
#pragma unroll
    for (int nf = 0; nf < 2; nf++) {
        int cb = d0 + wn + nf * 8 + 2 * tig;
        *(float2*)(Cb + (size_t)r0 * Ee + cb) = make_float2(acc[nf][0], acc[nf][1]);
        *(float2*)(Cb + (size_t)r1 * Ee + cb) = make_float2(acc[nf][2], acc[nf][3]);
    }
}

// combine per-row partials -> lse[row]
__global__ void k_lse_combine(const float2* __restrict__ part, int cnt, float* __restrict__ out) {
    int row = blockIdx.x;
    float mx = -1e30f, s = 0.f;
    for (int i = threadIdx.x; i < cnt; i += blockDim.x) {
        float2 p = part[(size_t)row * cnt + i];
        lse_merge(mx, s, p.x, p.y);
    }
#pragma unroll
    for (int o = 16; o; o >>= 1) {
        float om = __shfl_xor_sync(0xffffffffu, mx, o);
        float os = __shfl_xor_sync(0xffffffffu, s, o);
        lse_merge(mx, s, om, os);
    }
    __shared__ float rm[4], rs[4];
    int lane = threadIdx.x & 31, w = threadIdx.x >> 5;
    if (lane == 0) { rm[w] = mx; rs[w] = s; }
    __syncthreads();
    if (threadIdx.x == 0) {
        float M = rm[0], S = rs[0];
        for (int i = 1; i < (blockDim.x >> 5); i++) lse_merge(M, S, rm[i], rs[i]);
        out[row] = M + logf(S);
    }
}

// ---------------- other kernels ----------------
__global__ void k_embed(const int* __restrict__ x, const float* __restrict__ emb,
                        float* __restrict__ embedded, float* __restrict__ inputf) {
    int r = blockIdx.x;
    int tok = x[r];
    float4 v = ((const float4*)(emb + (size_t)tok * Ee))[threadIdx.x];
    ((float4*)(embedded + (size_t)r * Ee))[threadIdx.x] = v;
    ((float4*)(inputf   + (size_t)r * Ee))[threadIdx.x] = v;
}

__global__ void k_gru_combine(const float* __restrict__ gi, const float* __restrict__ gh,
                              const float* __restrict__ b_ih, const float* __restrict__ b_hh,
                              const float* __restrict__ h_in, float* __restrict__ h_out,
                              int N, float* __restrict__ out2,
                              const int* __restrict__ lengths, int dstep) {
    int idx = blockIdx.x * blockDim.x + threadIdx.x;
    if (idx >= N * Hh) return;
    int n = idx / Hh, k = idx - n * Hh;
    size_t base = (size_t)n * G3H;
    float ir = gi[base + k]           + b_ih[k];
    float iz = gi[base + Hh + k]      + b_ih[Hh + k];
    float in_ = gi[base + 2 * Hh + k] + b_ih[2 * Hh + k];
    float hr = gh[base + k]           + b_hh[k];
    float hz = gh[base + Hh + k]      + b_hh[Hh + k];
    float hn = gh[base + 2 * Hh + k]  + b_hh[2 * Hh + k];
    float r = sigmf(ir + hr);
    float z = sigmf(iz + hz);
    float nn = tanhf(in_ + r * hn);
    float val = (1.f - z) * nn + z * h_in[idx];
    h_out[idx] = val;
    if (out2) {
        int b = n / NTt, t = n - b * NTt;
        float v2 = (t + dstep < lengths[b]) ? val : 0.f;
        out2[idx] = v2;
    }
}

__global__ void k_wingather(const float* __restrict__ embedded, const int* __restrict__ lengths,
                            float* __restrict__ wins) {
    int r = blockIdx.x;
    int d = r & 3;
    int bt = r >> 2;
    int b = bt / NTt, t = bt - b * NTt;
    int idx = (t == 0 && d == 0) ? (lengths[b] - 1) : (t + d - 1);
    const float4* src = (const float4*)(embedded + ((size_t)b * Tt + idx) * Ee);
    float4* dst = (float4*)(wins + ((size_t)d * NDEC + bt) * Ee);
    dst[threadIdx.x] = src[threadIdx.x];
}

__global__ void k_h0(const float* __restrict__ inputf, float* __restrict__ h) {
    int n = blockIdx.x;
    int b = n / NTt, t = n - b * NTt;
    ((float4*)(h + (size_t)n * Hh))[threadIdx.x] =
        ((const float4*)(inputf + ((size_t)b * Tt + t) * Ee))[threadIdx.x];
}

// Head-region write: out row R reads permuted scratch row sr = d*NDEC + bt.
__global__ void k_write_head(const __half* __restrict__ hl, const float* __restrict__ lseh,
                             const int* __restrict__ lengths, float* __restrict__ out) {
    int row = blockIdx.y;
    int v4 = blockIdx.x * blockDim.x + threadIdx.x;
    if (v4 >= (C0c >> 2)) return;
    int d = row & 3;
    int bt = row >> 2;
    int sr = d * NDEC + bt;
    int b = bt / NTt, t = bt - b * NTt;
    float4* o = (float4*)(out + (size_t)row * Vv) + v4;
    if (t >= __ldg(lengths + b)) { __stcs(o, make_float4(0.f, 0.f, 0.f, 0.f)); return; }
    float c = -__ldg(lseh + sr);
    const __half* s = hl + (size_t)sr * HLDC + v4 * 4;
    float2 f01 = __half22float2(__ldg((const __half2*)(s)));
    float2 f23 = __half22float2(__ldg((const __half2*)(s + 2)));
    __stcs(o, make_float4(f01.x + c, f01.y + c, f23.x + c, f23.y + c));
}

// ---------------- host orchestration ----------------
extern "C" void kernel_launch(void* const* d_in, const int* in_sizes, int n_in,
                              void* d_out, int out_size) {
    const int*   x        = (const int*)d_in[0];
    const int*   lengths  = (const int*)d_in[1];
    const float* G        = (const float*)d_in[2];
    const float* emb      = (const float*)d_in[3];
    const float* enc_w_ih = (const float*)d_in[4];
    const float* enc_w_hh = (const float*)d_in[5];
    const float* enc_b_ih = (const float*)d_in[6];
    const float* enc_b_hh = (const float*)d_in[7];
    const float* dec_w_ih = (const float*)d_in[8];
    const float* dec_w_hh = (const float*)d_in[9];
    const float* dec_b_ih = (const float*)d_in[10];
    const float* dec_b_hh = (const float*)d_in[11];
    const float* head_w   = (const float*)d_in[12];
    const float* t0_proj  = (const float*)d_in[13];
    const float* t0_out   = (const float*)d_in[14];
    const float* t1_proj  = (const float*)d_in[15];
    const float* t1_out   = (const float*)d_in[16];
    float* out = (float*)d_out;

    float *embedded, *inputf, *wgt, *egi, *gi, *gh, *wins, *h, *hs, *z0, *z1;
    float *lh, *l0, *l1;
    __half *hl;
    float2 *ph, *p0, *p1;
    cudaGetSymbolAddress((void**)&embedded, g_embedded);
    cudaGetSymbolAddress((void**)&inputf,   g_inputf);
    cudaGetSymbolAddress((void**)&wgt,      g_wgt);
    cudaGetSymbolAddress((void**)&egi,      g_egi);
    cudaGetSymbolAddress((void**)&gi,       g_gi);
    cudaGetSymbolAddress((void**)&gh,       g_gh);
    cudaGetSymbolAddress((void**)&wins,     g_wins);
    cudaGetSymbolAddress((void**)&h,        g_h);
    cudaGetSymbolAddress((void**)&hs,       g_hs);
    cudaGetSymbolAddress((void**)&z0,       g_z0);
    cudaGetSymbolAddress((void**)&z1,       g_z1);
    cudaGetSymbolAddress((void**)&hl,       g_headlog);
    cudaGetSymbolAddress((void**)&lh,       g_lseh);
    cudaGetSymbolAddress((void**)&l0,       g_lse0);
    cudaGetSymbolAddress((void**)&l1,       g_lse1);
    cudaGetSymbolAddress((void**)&ph,       g_parth);
    cudaGetSymbolAddress((void**)&p0,       g_part0);
    cudaGetSymbolAddress((void**)&p1,       g_part1);

    static cudaStream_t s2 = 0, s3 = 0, s4 = 0;
    static cudaEvent_t eEmb = 0, eGi = 0, eHs2 = 0, eHs3 = 0;
    static cudaEvent_t eStep[4] = {0, 0, 0, 0};
    static cudaEvent_t eHead2 = 0, eHead3 = 0, eW2 = 0, eW3 = 0, eW4 = 0;
    if (!s2) {
        cudaStreamCreateWithFlags(&s2, cudaStreamNonBlocking);
        cudaStreamCreateWithFlags(&s3, cudaStreamNonBlocking);
        cudaStreamCreateWithFlags(&s4, cudaStreamNonBlocking);
        cudaEventCreateWithFlags(&eEmb,   cudaEventDisableTiming);
        cudaEventCreateWithFlags(&eGi,    cudaEventDisableTiming);
        cudaEventCreateWithFlags(&eHs2,   cudaEventDisableTiming);
        cudaEventCreateWithFlags(&eHs3,   cudaEventDisableTiming);
        for (int d = 0; d < 4; d++) cudaEventCreateWithFlags(&eStep[d], cudaEventDisableTiming);
        cudaEventCreateWithFlags(&eHead2, cudaEventDisableTiming);
        cudaEventCreateWithFlags(&eHead3, cudaEventDisableTiming);
        cudaEventCreateWithFlags(&eW2,    cudaEventDisableTiming);
        cudaEventCreateWithFlags(&eW3,    cudaEventDisableTiming);
        cudaEventCreateWithFlags(&eW4,    cudaEventDisableTiming);
    }

    // 1) embedding (main)
    k_embed<<<NENC, 128>>>(x, emb, embedded, inputf);
    cudaEventRecord(eEmb, 0);

    // s2: window gather + decoder-gi GEMM, concurrent with encoder
    cudaStreamWaitEvent(s2, eEmb, 0);
    k_wingather<<<NROW, 128, 0, s2>>>(embedded, lengths, wins);
    k_tf32_gemm<128, false, false, ST_F32><<<dim3(G3H / 128, (NROW + 127) / 128), 256, 0, s2>>>(
        wins, dec_w_ih, gi, 0, 0, 0, NROW, G3H, Ee, G3H, (float2*)0, 0, 0, 0, 0, 0, 0, 0);
    cudaEventRecord(eGi, s2);

    // main: encoder layers
    for (int l = 0; l < Ll; l++) {
        k_gt_tf32<<<dim3(Ee / 64, Tt / 32, Bb), 256>>>(G, l, inputf, wgt);
        dim3 gA(G3H / 128, NENC / 32, 2);
        k_tf32_gemm<32, true, false, ST_F32><<<gA, 256>>>(
            wgt,    enc_w_ih + (size_t)l * G3H * Hh, egi,
            inputf, enc_w_hh + (size_t)l * G3H * Hh, gh,
            NENC, G3H, Hh, G3H, (float2*)0, 0, 0, 0, 0, 0, 0, 0);
        k_gru_combine<<<(NENC * Hh + 255) / 256, 256>>>(egi, gh, enc_b_ih + l * G3H, enc_b_hh + l * G3H,
                                                        inputf, inputf, NENC, (float*)0, (int*)0, 0);
    }
    k_h0<<<NDEC, 128>>>(inputf, h);

    // join gi
    cudaStreamWaitEvent(0, eGi, 0);

    // decoder: 4 sequential GRU steps; head GEMM chunk per step on s4
    for (int d = 0; d < Dd; d++) {
        k_tf32_gemm<32, false, false, ST_F32><<<dim3(G3H / 128, (NDEC + 31) / 32), 256>>>(
            h, dec_w_hh, gh, 0, 0, 0, NDEC, G3H, Hh, G3H, (float2*)0, 0, 0, 0, 0, 0, 0, 0);
        k_gru_combine<<<(NDEC * Hh + 255) / 256, 256>>>(
            gi + (size_t)d * NDEC * G3H, gh, dec_b_ih, dec_b_hh,
            h, h, NDEC, hs + (size_t)d * NDEC * Hh, lengths, d);
        cudaEventRecord(eStep[d], 0);
        cudaStreamWaitEvent(s4, eStep[d], 0);
        k_tf32_gemm<64, false, true, ST_F16><<<dim3(16, (NDEC + 63) / 64), 256, 0, s4>>>(
            hs + (size_t)d * NDEC * Hh, head_w, hl + (size_t)d * NDEC * HLDC,
            0, 0, 0, NDEC, 2002, Hh, HLDC, ph + (size_t)d * NDEC * PH, PH, 0, 0, 0, 0, 0, 0);
    }
    cudaEventRecord(eHs2, 0);
    cudaEventRecord(eHs3, 0);

    // s4: head LSE combine + head-region write
    k_lse_combine<<<NROW, 128, 0, s4>>>(ph, PH, lh);
    cudaEventRecord(eHead2, s4);
    cudaEventRecord(eHead3, s4);
    k_write_head<<<dim3(2, NROW), 256, 0, s4>>>(hl, lh, lengths, out);
    cudaEventRecord(eW4, s4);

    // s2: t0 chain — proj, LSE pass (no store), combine, direct-out pass
    cudaStreamWaitEvent(s2, eHs2, 0);
    k_tf32_gemm<128, false, false, ST_F32><<<dim3(1, (NROW + 127) / 128), 256, 0, s2>>>(
        hs, t0_proj, z0, 0, 0, 0, NROW, 128, Hh, 128, (float2*)0, 0, 0, 0, 0, 0, 0, 0);
    k_tf32_gemm<128, false, true, ST_NONE><<<dim3(63, (NROW + 127) / 128), 256, 0, s2>>>(
        z0, t0_out, 0, 0, 0, 0, NROW, W0, 128, 0, p0, P0, 0, 0, 0, 0, 0, 0);
    k_lse_combine<<<NROW, 128, 0, s2>>>(p0, P0, l0);
    cudaStreamWaitEvent(s2, eHead2, 0);
    k_tf32_gemm<128, false, false, ST_OUTS><<<dim3(63, (NROW + 127) / 128), 256, 0, s2>>>(
        z0, t0_out, out, 0, 0, 0, NROW, W0, 128, 0, (float2*)0, 0,
        C0c, hl, C0c, lh, l0, lengths);
    cudaEventRecord(eW2, s2);

    // s3: t1 chain — proj, LSE pass, combine, direct-out pass
    cudaStreamWaitEvent(s3, eHs3, 0);
    k_tf32_gemm<128, false, false, ST_F32><<<dim3(1, (NROW + 127) / 128), 256, 0, s3>>>(
        hs, t1_proj, z1, 0, 0, 0, NROW, 32, Hh, 32, (float2*)0, 0, 0, 0, 0, 0, 0, 0);
    k_tf32_gemm<128, false, true, ST_NONE><<<dim3(172, (NROW + 127) / 128), 256, 0, s3>>>(
        z1, t1_out, 0, 0, 0, 0, NROW, W1, 32, 0, p1, P1, 0, 0, 0, 0, 0, 0);
    k_lse_combine<<<NROW, 128, 0, s3>>>(p1, P1, l1);
    cudaStreamWaitEvent(s3, eHead3, 0);
    k_tf32_gemm<128, false, false, ST_OUTS><<<dim3(172, (NROW + 127) / 128), 256, 0, s3>>>(
        z1, t1_out, out, 0, 0, 0, NROW, W1, 32, 0, (float2*)0, 0,
        C1c, hl, C0c + 1, lh, l1, lengths);
    cudaEventRecord(eW3, s3);

    // join everything back to main
    cudaStreamWaitEvent(0, eW2, 0);
    cudaStreamWaitEvent(0, eW3, 0);
    cudaStreamWaitEvent(0, eW4, 0);
}

// round 15
// speedup vs baseline: 1.2241x; 1.2241x over previous
#include <cuda_runtime.h>
#include <cuda_fp16.h>
#include <math.h>
#include <stdint.h>

// Problem constants
#define Vv    32000
#define Ee    512
#define Hh    512
#define Tt    128
#define Bb    4
#define Dd    4
#define Ll    2
#define C0c   2000
#define C1c   10000
#define NTt   125            // T - D + 1
#define NROW  2000           // B*NT*D
#define NDEC  500            // B*NT
#define NENC  512            // B*T
#define G3H   1536           // 3*H
#define HLDC  2004           // padded head-logit row stride
#define W0    8000           // C1-C0
#define W1    22000          // V-C1

// partial-LSE strides
#define PH    64
#define P0    252
#define P1    688

// ---------------- device scratch ----------------
// hs layout: [d][NDEC][H] (step-major). Output row R = bt*4+d -> scratch row sr = d*NDEC+bt.
__device__ float g_embedded[NENC * Ee];
__device__ float g_inputf[NENC * Ee];
__device__ float g_wgt[NENC * Ee];
__device__ float g_egi[NENC * G3H];
__device__ float g_gi[NROW * G3H];
__device__ float g_gh[NENC * G3H];
__device__ float g_wins[Dd * NDEC * Ee];
__device__ float g_h[NDEC * Hh];
__device__ float g_hs[NROW * Hh];
__device__ float g_z0[NROW * 128];
__device__ float g_z1[NROW * 32];
__device__ __half g_headlog[NROW * HLDC];
__device__ __half g_t0log[(size_t)NROW * W0];
__device__ __half g_t1log[(size_t)NROW * W1];
__device__ float g_lseh[NROW];
__device__ float g_lse0[NROW];
__device__ float g_lse1[NROW];
__device__ float2 g_parth[NROW * PH];
__device__ float2 g_part0[NROW * P0];
__device__ float2 g_part1[NROW * P1];

// ---------------- tf32 helpers ----------------
__device__ __forceinline__ uint32_t f2tf(float f) {
    uint32_t u;
    asm("cvt.rna.tf32.f32 %0, %1;" : "=r"(u) : "f"(f));
    return u;
}

__device__ __forceinline__ void mma_tf32(float* d, const uint32_t* a, const uint32_t* b) {
    asm volatile(
        "mma.sync.aligned.m16n8k8.row.col.f32.tf32.tf32.f32 "
        "{%0,%1,%2,%3}, {%4,%5,%6,%7}, {%8,%9}, {%0,%1,%2,%3};"
        : "+f"(d[0]), "+f"(d[1]), "+f"(d[2]), "+f"(d[3])
        : "r"(a[0]), "r"(a[1]), "r"(a[2]), "r"(a[3]), "r"(b[0]), "r"(b[1]));
}

__device__ __forceinline__ void lse_merge(float& m, float& s, float om, float os) {
    float M = fmaxf(m, om);
    s = s * expf(m - M) + os * expf(om - M);
    m = M;
}

__device__ __forceinline__ float sigmf(float v) { return 1.f / (1.f + expf(-v)); }

// ---------------- generic tf32 GEMM: C[M,N] = A[M,K] * B[N,K]^T ----------------
template <int BM, bool DUAL, bool FUSE_LSE, bool HALF>
__global__ void __launch_bounds__(256)
k_tf32_gemm(const float* __restrict__ A0, const float* __restrict__ B0, void* __restrict__ C0p,
            const float* __restrict__ A1, const float* __restrict__ B1, void* __restrict__ C1p,
            int M, int N, int K, int ldc, float2* __restrict__ part, int pstride) {
    const float* A = (DUAL && blockIdx.z) ? A1 : A0;
    const float* B = (DUAL && blockIdx.z) ? B1 : B0;
    void*      Cp = (DUAL && blockIdx.z) ? C1p : C0p;

    constexpr int MF = BM / 32;
    constexpr int PA = BM / 32;
    __shared__ uint32_t As[BM * 32];
    __shared__ uint32_t Bs[128 * 32];

    int tid = threadIdx.x;
    int lane = tid & 31, wid = tid >> 5;
    int tig = lane & 3, grp4 = lane >> 2;
    int wm = (wid & 1) * (BM / 2);
    int wn = (wid >> 1) * 32;
    int m0 = blockIdx.y * BM, n0 = blockIdx.x * 128;

    float acc[MF][4][4];
#pragma unroll
    for (int i = 0; i < MF; i++)
#pragma unroll
        for (int j = 0; j < 4; j++)
#pragma unroll
            for (int k = 0; k < 4; k++) acc[i][j][k] = 0.f;

    int aRow[PA], aGrp[PA], aOk[PA];
    const float* aPtr[PA];
    int bRow[4], bGrp[4], bOk[4];
    const float* bPtr[4];
#pragma unroll
    for (int p = 0; p < PA; p++) {
        int idx = tid + p * 256;
        aRow[p] = idx >> 3; aGrp[p] = idx & 7;
        int gm = m0 + aRow[p];
        aOk[p] = (gm < M);
        aPtr[p] = A + (size_t)(aOk[p] ? gm : 0) * K + aGrp[p] * 4;
    }
#pragma unroll
    for (int p = 0; p < 4; p++) {
        int idx = tid + p * 256;
        bRow[p] = idx >> 3; bGrp[p] = idx & 7;
        int gn = n0 + bRow[p];
        bOk[p] = (gn < N);
        bPtr[p] = B + (size_t)(bOk[p] ? gn : 0) * K + bGrp[p] * 4;
    }

    const float4 z4 = make_float4(0.f, 0.f, 0.f, 0.f);
    float4 pa[PA], pb[4];
#pragma unroll
    for (int p = 0; p < PA; p++) pa[p] = aOk[p] ? *(const float4*)(aPtr[p]) : z4;
#pragma unroll
    for (int p = 0; p < 4; p++)  pb[p] = bOk[p] ? *(const float4*)(bPtr[p]) : z4;

    int nk = K >> 5;
    for (int ks = 0; ks < nk; ks++) {
#pragma unroll
        for (int p = 0; p < PA; p++) {
            uint32_t* d = &As[aRow[p] * 32 + ((aGrp[p] ^ (aRow[p] & 7)) << 2)];
            *(uint4*)d = make_uint4(f2tf(pa[p].x), f2tf(pa[p].y), f2tf(pa[p].z), f2tf(pa[p].w));
        }
#pragma unroll
        for (int p = 0; p < 4; p++) {
            uint32_t* d = &Bs[bRow[p] * 32 + ((bGrp[p] ^ (bRow[p] & 7)) << 2)];
            *(uint4*)d = make_uint4(f2tf(pb[p].x), f2tf(pb[p].y), f2tf(pb[p].z), f2tf(pb[p].w));
        }
        __syncthreads();

        if (ks + 1 < nk) {
            int off = (ks + 1) * 32;
#pragma unroll
            for (int p = 0; p < PA; p++) pa[p] = aOk[p] ? *(const float4*)(aPtr[p] + off) : z4;
#pragma unroll
            for (int p = 0; p < 4; p++)  pb[p] = bOk[p] ? *(const float4*)(bPtr[p] + off) : z4;
        }

#pragma unroll
        for (int kk = 0; kk < 4; kk++) {
            int g0 = kk * 2, g1 = kk * 2 + 1;
            uint32_t a[MF][4], b[4][2];
#pragma unroll
            for (int mf = 0; mf < MF; mf++) {
                int r = wm + mf * 16 + grp4;
                int base = r * 32 + tig;
                int s0 = (g0 ^ (r & 7)) << 2;
                int s1 = (g1 ^ (r & 7)) << 2;
                a[mf][0] = As[base + s0];
                a[mf][1] = As[base + 256 + s0];
                a[mf][2] = As[base + s1];
                a[mf][3] = As[base + 256 + s1];
            }
#pragma unroll
            for (int nf = 0; nf < 4; nf++) {
                int rn = wn + nf * 8 + grp4;
                int base = rn * 32 + tig;
                b[nf][0] = Bs[base + ((g0 ^ (rn & 7)) << 2)];
                b[nf][1] = Bs[base + ((g1 ^ (rn & 7)) << 2)];
            }
#pragma unroll
            for (int mf = 0; mf < MF; mf++)
#pragma unroll
                for (int nf = 0; nf < 4; nf++)
                    mma_tf32(acc[mf][nf], a[mf], b[nf]);
        }
        __syncthreads();
    }

#pragma unroll
    for (int mf = 0; mf < MF; mf++) {
        int r0 = m0 + wm + mf * 16 + grp4;
        int r1 = r0 + 8;
#pragma unroll
        for (int nf = 0; nf < 4; nf++) {
            int cb = n0 + wn + nf * 8 + 2 * tig;
            if (cb >= N) continue;
            if (HALF) {
                __half* C = (__half*)Cp;
                if (r0 < M) *(__half2*)(C + (size_t)r0 * ldc + cb) =
                    __floats2half2_rn(acc[mf][nf][0], acc[mf][nf][1]);
                if (r1 < M) *(__half2*)(C + (size_t)r1 * ldc + cb) =
                    __floats2half2_rn(acc[mf][nf][2], acc[mf][nf][3]);
            } else {
                float* C = (float*)Cp;
                if (r0 < M) *(float2*)(C + (size_t)r0 * ldc + cb) = make_float2(acc[mf][nf][0], acc[mf][nf][1]);
                if (r1 < M) *(float2*)(C + (size_t)r1 * ldc + cb) = make_float2(acc[mf][nf][2], acc[mf][nf][3]);
            }
        }
    }

    if (FUSE_LSE) {
        int xc = blockIdx.x * 4 + (wid >> 1);
#pragma unroll
        for (int mf = 0; mf < MF; mf++) {
#pragma unroll
            for (int half = 0; half < 2; half++) {
                int row = m0 + wm + mf * 16 + grp4 + half * 8;
                float mx = -1e30f;
#pragma unroll
                for (int nf = 0; nf < 4; nf++) {
                    int cb = n0 + wn + nf * 8 + 2 * tig;
                    if (cb < N)     mx = fmaxf(mx, acc[mf][nf][half * 2]);
                    if (cb + 1 < N) mx = fmaxf(mx, acc[mf][nf][half * 2 + 1]);
                }
                mx = fmaxf(mx, __shfl_xor_sync(0xffffffffu, mx, 1));
                mx = fmaxf(mx, __shfl_xor_sync(0xffffffffu, mx, 2));
                float s = 0.f;
#pragma unroll
                for (int nf = 0; nf < 4; nf++) {
                    int cb = n0 + wn + nf * 8 + 2 * tig;
                    if (cb < N)     s += expf(acc[mf][nf][half * 2]     - mx);
                    if (cb + 1 < N) s += expf(acc[mf][nf][half * 2 + 1] - mx);
                }
                s += __shfl_xor_sync(0xffffffffu, s, 1);
                s += __shfl_xor_sync(0xffffffffu, s, 2);
                if (tig == 0 && row < M)
                    part[(size_t)row * pstride + xc] = make_float2(mx, s);
            }
        }
    }
}

// ---------------- tf32 einsum, small tiles for full-chip occupancy ----------------
__global__ void __launch_bounds__(256)
k_gt_tf32(const float* __restrict__ G, int l, const float* __restrict__ X, float* __restrict__ C) {
    int b  = blockIdx.z;
    int i0 = blockIdx.y * 32;
    int d0 = blockIdx.x * 64;
    const float* Gb = G + ((size_t)b * Ll + l) * Tt * Tt;
    const float* Xb = X + (size_t)b * Tt * Ee;

    __shared__ uint32_t As[32 * 32];
    __shared__ uint32_t Bs[64 * 32];

    int tid = threadIdx.x;
    int lane = tid & 31, wid = tid >> 5;
    int tig = lane & 3, grp4 = lane >> 2;
    int wm = (wid & 1) * 16;
    int wn = (wid >> 1) * 16;

    float acc[2][4];
#pragma unroll
    for (int j = 0; j < 2; j++)
#pragma unroll
        for (int k = 0; k < 4; k++) acc[j][k] = 0.f;

    int jlA = tid & 31, i4A = tid >> 5;
    int jlB[2], d4B[2];
#pragma unroll
    for (int p = 0; p < 2; p++) { int idx = tid + p * 256; jlB[p] = idx & 31; d4B[p] = idx >> 5; }

    float4 ga, xa[2];
    ga = *(const float4*)(Gb + (size_t)jlA * Tt + i0 + i4A * 4);
#pragma unroll
    for (int p = 0; p < 2; p++) xa[p] = *(const float4*)(Xb + (size_t)jlB[p] * Ee + d0 + d4B[p] * 4);

    for (int ks = 0; ks < 4; ks++) {
        {
            int grp = jlA >> 2, t = jlA & 3;
            float gv[4] = {ga.x, ga.y, ga.z, ga.w};
#pragma unroll
            for (int q = 0; q < 4; q++) {
                int r = i4A * 4 + q;
                As[r * 32 + ((grp ^ (r & 7)) << 2) + t] = f2tf(gv[q]);
            }
        }
#pragma unroll
        for (int p = 0; p < 2; p++) {
            int grp = jlB[p] >> 2, t = jlB[p] & 3;
            float xf[4] = {xa[p].x, xa[p].y, xa[p].z, xa[p].w};
#pragma unroll
            for (int q = 0; q < 4; q++) {
                int r = d4B[p] * 4 + q;
                Bs[r * 32 + ((grp ^ (r & 7)) << 2) + t] = f2tf(xf[q]);
            }
        }
        __syncthreads();

        if (ks < 3) {
            int j0 = (ks + 1) * 32;
            ga = *(const float4*)(Gb + (size_t)(j0 + jlA) * Tt + i0 + i4A * 4);
#pragma unroll
            for (int p = 0; p < 2; p++) xa[p] = *(const float4*)(Xb + (size_t)(j0 + jlB[p]) * Ee + d0 + d4B[p] * 4);
        }

#pragma unroll
        for (int kk = 0; kk < 4; kk++) {
            int g0 = kk * 2, g1 = kk * 2 + 1;
            uint32_t a[4], bb[2][2];
            {
                int r = wm + grp4;
                int base = r * 32 + tig;
                int s0 = (g0 ^ (r & 7)) << 2;
                int s1 = (g1 ^ (r & 7)) << 2;
                a[0] = As[base + s0];
                a[1] = As[base + 256 + s0];
                a[2] = As[base + s1];
                a[3] = As[base + 256 + s1];
            }
#pragma unroll
            for (int nf = 0; nf < 2; nf++) {
                int rn = wn + nf * 8 + grp4;
                int base = rn * 32 + tig;
                bb[nf][0] = Bs[base + ((g0 ^ (rn & 7)) << 2)];
                bb[nf][1] = Bs[base + ((g1 ^ (rn & 7)) << 2)];
            }
#pragma unroll
            for (int nf = 0; nf < 2; nf++)
                mma_tf32(acc[nf], a, bb[nf]);
        }
        __syncthreads();
    }

    float* Cb = C + (size_t)b * Tt * Ee;
    int r0 = i0 + wm + grp4;
    int r1 = r0 + 8;
#pragma unroll
    for (int nf = 0; nf < 2; nf++) {
        int cb = d0 + wn + nf * 8 + 2 * tig;
        *(float2*)(Cb + (size_t)r0 * Ee + cb) = make_float2(acc[nf][0], acc[nf][1]);
        *(float2*)(Cb + (size_t)r1 * Ee + cb) = make_float2(acc[nf][2], acc[nf][3]);
    }
}

// combine per-row partials -> lse[row]
__global__ void k_lse_combine(const float2* __restrict__ part, int cnt, float* __restrict__ out) {
    int row = blockIdx.x;
    float mx = -1e30f, s = 0.f;
    for (int i = threadIdx.x; i < cnt; i += blockDim.x) {
        float2 p = part[(size_t)row * cnt + i];
        lse_merge(mx, s, p.x, p.y);
    }
#pragma unroll
    for (int o = 16; o; o >>= 1) {
        float om = __shfl_xor_sync(0xffffffffu, mx, o);
        float os = __shfl_xor_sync(0xffffffffu, s, o);
        lse_merge(mx, s, om, os);
    }
    __shared__ float rm[4], rs[4];
    int lane = threadIdx.x & 31, w = threadIdx.x >> 5;
    if (lane == 0) { rm[w] = mx; rs[w] = s; }
    __syncthreads();
    if (threadIdx.x == 0) {
        float M = rm[0], S = rs[0];
        for (int i = 1; i < (blockDim.x >> 5); i++) lse_merge(M, S, rm[i], rs[i]);
        out[row] = M + logf(S);
    }
}

// ---------------- other kernels ----------------
__global__ void k_embed(const int* __restrict__ x, const float* __restrict__ emb,
                        float* __restrict__ embedded, float* __restrict__ inputf) {
    int r = blockIdx.x;
    int tok = x[r];
    float4 v = ((const float4*)(emb + (size_t)tok * Ee))[threadIdx.x];
    ((float4*)(embedded + (size_t)r * Ee))[threadIdx.x] = v;
    ((float4*)(inputf   + (size_t)r * Ee))[threadIdx.x] = v;
}

__global__ void k_gru_combine(const float* __restrict__ gi, const float* __restrict__ gh,
                              const float* __restrict__ b_ih, const float* __restrict__ b_hh,
                              const float* __restrict__ h_in, float* __restrict__ h_out,
                              int N, float* __restrict__ out2,
                              const int* __restrict__ lengths, int dstep) {
    int idx = blockIdx.x * blockDim.x + threadIdx.x;
    if (idx >= N * Hh) return;
    int n = idx / Hh, k = idx - n * Hh;
    size_t base = (size_t)n * G3H;
    float ir = gi[base + k]           + b_ih[k];
    float iz = gi[base + Hh + k]      + b_ih[Hh + k];
    float in_ = gi[base + 2 * Hh + k] + b_ih[2 * Hh + k];
    float hr = gh[base + k]           + b_hh[k];
    float hz = gh[base + Hh + k]      + b_hh[Hh + k];
    float hn = gh[base + 2 * Hh + k]  + b_hh[2 * Hh + k];
    float r = sigmf(ir + hr);
    float z = sigmf(iz + hz);
    float nn = tanhf(in_ + r * hn);
    float val = (1.f - z) * nn + z * h_in[idx];
    h_out[idx] = val;
    if (out2) {
        int b = n / NTt, t = n - b * NTt;
        float v2 = (t + dstep < lengths[b]) ? val : 0.f;
        out2[idx] = v2;
    }
}

__global__ void k_wingather(const float* __restrict__ embedded, const int* __restrict__ lengths,
                            float* __restrict__ wins) {
    int r = blockIdx.x;
    int d = r & 3;
    int bt = r >> 2;
    int b = bt / NTt, t = bt - b * NTt;
    int idx = (t == 0 && d == 0) ? (lengths[b] - 1) : (t + d - 1);
    const float4* src = (const float4*)(embedded + ((size_t)b * Tt + idx) * Ee);
    float4* dst = (float4*)(wins + ((size_t)d * NDEC + bt) * Ee);
    dst[threadIdx.x] = src[threadIdx.x];
}

__global__ void k_h0(const float* __restrict__ inputf, float* __restrict__ h) {
    int n = blockIdx.x;
    int b = n / NTt, t = n - b * NTt;
    ((float4*)(h + (size_t)n * Hh))[threadIdx.x] =
        ((const float4*)(inputf + ((size_t)b * Tt + t) * Ee))[threadIdx.x];
}

// Region write: out row R (= bt*4+d) reads permuted scratch row sr = d*NDEC + bt.
__global__ void k_write_region(const __half* __restrict__ src, int srcStride,
                               int colStart, int width,
                               const __half* __restrict__ hl, int headcol,
                               const float* __restrict__ lseh, const float* __restrict__ lse2,
                               const int* __restrict__ lengths, float* __restrict__ out) {
    int row = blockIdx.y;
    int v4 = blockIdx.x * blockDim.x + threadIdx.x;
    if (v4 >= (width >> 2)) return;
    int d = row & 3;
    int bt = row >> 2;
    int sr = d * NDEC + bt;
    int b = bt / NTt, t = bt - b * NTt;
    float4* o = (float4*)(out + (size_t)row * Vv + colStart) + v4;
    if (t >= __ldg(lengths + b)) { __stcs(o, make_float4(0.f, 0.f, 0.f, 0.f)); return; }
    float c = -__ldg(lseh + sr);
    if (lse2)
        c += __half2float(__ldg(hl + (size_t)sr * HLDC + headcol)) - __ldg(lse2 + sr);
    const __half* s = src + (size_t)sr * srcStride + v4 * 4;
    float2 f01 = __half22float2(__ldg((const __half2*)(s)));
    float2 f23 = __half22float2(__ldg((const __half2*)(s + 2)));
    __stcs(o, make_float4(f01.x + c, f01.y + c, f23.x + c, f23.y + c));
}

// ---------------- host orchestration ----------------
extern "C" void kernel_launch(void* const* d_in, const int* in_sizes, int n_in,
                              void* d_out, int out_size) {
    const int*   x        = (const int*)d_in[0];
    const int*   lengths  = (const int*)d_in[1];
    const float* G        = (const float*)d_in[2];
    const float* emb      = (const float*)d_in[3];
    const float* enc_w_ih = (const float*)d_in[4];
    const float* enc_w_hh = (const float*)d_in[5];
    const float* enc_b_ih = (const float*)d_in[6];
    const float* enc_b_hh = (const float*)d_in[7];
    const float* dec_w_ih = (const float*)d_in[8];
    const float* dec_w_hh = (const float*)d_in[9];
    const float* dec_b_ih = (const float*)d_in[10];
    const float* dec_b_hh = (const float*)d_in[11];
    const float* head_w   = (const float*)d_in[12];
    const float* t0_proj  = (const float*)d_in[13];
    const float* t0_out   = (const float*)d_in[14];
    const float* t1_proj  = (const float*)d_in[15];
    const float* t1_out   = (const float*)d_in[16];
    float* out = (float*)d_out;

    float *embedded, *inputf, *wgt, *egi, *gi, *gh, *wins, *h, *hs, *z0, *z1;
    float *lh, *l0, *l1;
    __half *hl, *t0l, *t1l;
    float2 *ph, *p0, *p1;
    cudaGetSymbolAddress((void**)&embedded, g_embedded);
    cudaGetSymbolAddress((void**)&inputf,   g_inputf);
    cudaGetSymbolAddress((void**)&wgt,      g_wgt);
    cudaGetSymbolAddress((void**)&egi,      g_egi);
    cudaGetSymbolAddress((void**)&gi,       g_gi);
    cudaGetSymbolAddress((void**)&gh,       g_gh);
    cudaGetSymbolAddress((void**)&wins,     g_wins);
    cudaGetSymbolAddress((void**)&h,        g_h);
    cudaGetSymbolAddress((void**)&hs,       g_hs);
    cudaGetSymbolAddress((void**)&z0,       g_z0);
    cudaGetSymbolAddress((void**)&z1,       g_z1);
    cudaGetSymbolAddress((void**)&hl,       g_headlog);
    cudaGetSymbolAddress((void**)&t0l,      g_t0log);
    cudaGetSymbolAddress((void**)&t1l,      g_t1log);
    cudaGetSymbolAddress((void**)&lh,       g_lseh);
    cudaGetSymbolAddress((void**)&l0,       g_lse0);
    cudaGetSymbolAddress((void**)&l1,       g_lse1);
    cudaGetSymbolAddress((void**)&ph,       g_parth);
    cudaGetSymbolAddress((void**)&p0,       g_part0);
    cudaGetSymbolAddress((void**)&p1,       g_part1);

    static cudaStream_t s2 = 0, s3 = 0, s4 = 0;
    static cudaEvent_t eEmb = 0, eGi = 0, eHs2 = 0, eHs3 = 0;
    static cudaEvent_t eStep[4] = {0, 0, 0, 0};
    static cudaEvent_t eHead2 = 0, eHead3 = 0, eW2 = 0, eW3 = 0, eW4 = 0;
    if (!s2) {
        cudaStreamCreateWithFlags(&s2, cudaStreamNonBlocking);
        cudaStreamCreateWithFlags(&s3, cudaStreamNonBlocking);
        cudaStreamCreateWithFlags(&s4, cudaStreamNonBlocking);
        cudaEventCreateWithFlags(&eEmb,   cudaEventDisableTiming);
        cudaEventCreateWithFlags(&eGi,    cudaEventDisableTiming);
        cudaEventCreateWithFlags(&eHs2,   cudaEventDisableTiming);
        cudaEventCreateWithFlags(&eHs3,   cudaEventDisableTiming);
        for (int d = 0; d < 4; d++) cudaEventCreateWithFlags(&eStep[d], cudaEventDisableTiming);
        cudaEventCreateWithFlags(&eHead2, cudaEventDisableTiming);
        cudaEventCreateWithFlags(&eHead3, cudaEventDisableTiming);
        cudaEventCreateWithFlags(&eW2,    cudaEventDisableTiming);
        cudaEventCreateWithFlags(&eW3,    cudaEventDisableTiming);
        cudaEventCreateWithFlags(&eW4,    cudaEventDisableTiming);
    }

    // 1) embedding (main)
    k_embed<<<NENC, 128>>>(x, emb, embedded, inputf);
    cudaEventRecord(eEmb, 0);

    // side stream s2: window gather + decoder-gi GEMM, concurrent with encoder
    cudaStreamWaitEvent(s2, eEmb, 0);
    k_wingather<<<NROW, 128, 0, s2>>>(embedded, lengths, wins);
    k_tf32_gemm<128, false, false, false><<<dim3(G3H / 128, (NROW + 127) / 128), 256, 0, s2>>>(
        wins, dec_w_ih, gi, 0, 0, 0, NROW, G3H, Ee, G3H, (float2*)0, 0);
    cudaEventRecord(eGi, s2);

    // main: encoder layers (gt einsum: 128-block small-tile version)
    for (int l = 0; l < Ll; l++) {
        k_gt_tf32<<<dim3(Ee / 64, Tt / 32, Bb), 256>>>(G, l, inputf, wgt);
        dim3 gA(G3H / 128, NENC / 32, 2);
        k_tf32_gemm<32, true, false, false><<<gA, 256>>>(
            wgt,    enc_w_ih + (size_t)l * G3H * Hh, egi,
            inputf, enc_w_hh + (size_t)l * G3H * Hh, gh,
            NENC, G3H, Hh, G3H, (float2*)0, 0);
        k_gru_combine<<<(NENC * Hh + 255) / 256, 256>>>(egi, gh, enc_b_ih + l * G3H, enc_b_hh + l * G3H,
                                                        inputf, inputf, NENC, (float*)0, (int*)0, 0);
    }
    k_h0<<<NDEC, 128>>>(inputf, h);

    // join gi
    cudaStreamWaitEvent(0, eGi, 0);

    // decoder: 4 sequential GRU steps; small-grid chunks under its shadow:
    //   s4: head GEMM chunk (16 blocks)  s2: t0 proj chunk (4 blocks)  s3: t1 proj chunk (4 blocks)
    for (int d = 0; d < Dd; d++) {
        k_tf32_gemm<32, false, false, false><<<dim3(G3H / 128, (NDEC + 31) / 32), 256>>>(
            h, dec_w_hh, gh, 0, 0, 0, NDEC, G3H, Hh, G3H, (float2*)0, 0);
        k_gru_combine<<<(NDEC * Hh + 255) / 256, 256>>>(
            gi + (size_t)d * NDEC * G3H, gh, dec_b_ih, dec_b_hh,
            h, h, NDEC, hs + (size_t)d * NDEC * Hh, lengths, d);
        cudaEventRecord(eStep[d], 0);

        const float* hsd = hs + (size_t)d * NDEC * Hh;

        cudaStreamWaitEvent(s4, eStep[d], 0);
        k_tf32_gemm<64, false, true, true><<<dim3(16, (NDEC + 63) / 64), 256, 0, s4>>>(
            hsd, head_w, hl + (size_t)d * NDEC * HLDC,
            0, 0, 0, NDEC, 2002, Hh, HLDC, ph + (size_t)d * NDEC * PH, PH);

        cudaStreamWaitEvent(s2, eStep[d], 0);
        k_tf32_gemm<128, false, false, false><<<dim3(1, (NDEC + 127) / 128), 256, 0, s2>>>(
            hsd, t0_proj, z0 + (size_t)d * NDEC * 128,
            0, 0, 0, NDEC, 128, Hh, 128, (float2*)0, 0);

        cudaStreamWaitEvent(s3, eStep[d], 0);
        k_tf32_gemm<128, false, false, false><<<dim3(1, (NDEC + 127) / 128), 256, 0, s3>>>(
            hsd, t1_proj, z1 + (size_t)d * NDEC * 32,
            0, 0, 0, NDEC, 32, Hh, 32, (float2*)0, 0);
    }
    cudaEventRecord(eHs2, 0);
    cudaEventRecord(eHs3, 0);

    // s4: head LSE combine (all chunks done in-order on s4) + head-region write
    k_lse_combine<<<NROW, 128, 0, s4>>>(ph, PH, lh);
    cudaEventRecord(eHead2, s4);
    cudaEventRecord(eHead3, s4);
    k_write_region<<<dim3(2, NROW), 256, 0, s4>>>(hl, HLDC, 0, C0c, hl, 0, lh, (float*)0, lengths, out);
    cudaEventRecord(eW4, s4);

    // s2: t0 logits (full) + combine + write
    k_tf32_gemm<128, false, true, true><<<dim3(63, (NROW + 127) / 128), 256, 0, s2>>>(
        z0, t0_out, t0l, 0, 0, 0, NROW, W0, 128, W0, p0, P0);
    k_lse_combine<<<NROW, 128, 0, s2>>>(p0, P0, l0);
    cudaStreamWaitEvent(s2, eHead2, 0);
    k_write_region<<<dim3(8, NROW), 256, 0, s2>>>(t0l, W0, C0c, W0, hl, C0c, lh, l0, lengths, out);
    cudaEventRecord(eW2, s2);

    // s3: t1 logits (full) + combine + write
    k_tf32_gemm<128, false, true, true><<<dim3(172, (NROW + 127) / 128), 256, 0, s3>>>(
        z1, t1_out, t1l, 0, 0, 0, NROW, W1, 32, W1, p1, P1);
    k_lse_combine<<<NROW, 128, 0, s3>>>(p1, P1, l1);
    cudaStreamWaitEvent(s3, eHead3, 0);
    k_write_region<<<dim3(22, NROW), 256, 0, s3>>>(t1l, W1, C1c, W1, hl, C0c + 1, lh, l1, lengths, out);
    cudaEventRecord(eW3, s3);

    // join everything back to main
    cudaStreamWaitEvent(0, eW2, 0);
    cudaStreamWaitEvent(0, eW3, 0);
    cudaStreamWaitEvent(0, eW4, 0);
}

// round 16
// speedup vs baseline: 1.2314x; 1.0060x over previous
#include <cuda_runtime.h>
#include <cuda_fp16.h>
#include <math.h>
#include <stdint.h>

// Problem constants
#define Vv    32000
#define Ee    512
#define Hh    512
#define Tt    128
#define Bb    4
#define Dd    4
#define Ll    2
#define C0c   2000
#define C1c   10000
#define NTt   125            // T - D + 1
#define NROW  2000           // B*NT*D
#define NDEC  500            // B*NT
#define NENC  512            // B*T
#define G3H   1536           // 3*H
#define HLDC  2004           // padded head-logit row stride
#define W0    8000           // C1-C0
#define W1    22000          // V-C1

// partial-LSE strides
#define PH    64
#define P0    252
#define P1    688

// ---------------- device scratch ----------------
// hs layout: [d][NDEC][H] (step-major). Output row R = bt*4+d -> scratch row sr = d*NDEC+bt.
__device__ float g_embedded[NENC * Ee];
__device__ float g_inputf[NENC * Ee];
__device__ float g_wgt[NENC * Ee];
__device__ float g_egi[NENC * G3H];
__device__ float g_gi[NROW * G3H];
__device__ float g_gh[NENC * G3H];
__device__ float g_wins[Dd * NDEC * Ee];
__device__ float g_h[NDEC * Hh];
__device__ float g_hs[NROW * Hh];
__device__ float g_z0[NROW * 128];
__device__ float g_z1[NROW * 32];
__device__ __half g_headlog[NROW * HLDC];
__device__ __half g_t0log[(size_t)NROW * W0];
__device__ __half g_t1log[(size_t)NROW * W1];
__device__ float g_lseh[NROW];
__device__ float g_lse0[NROW];
__device__ float g_lse1[NROW];
__device__ float2 g_parth[NROW * PH];
__device__ float2 g_part0[NROW * P0];
__device__ float2 g_part1[NROW * P1];

// ---------------- tf32 helpers ----------------
__device__ __forceinline__ uint32_t f2tf(float f) {
    uint32_t u;
    asm("cvt.rna.tf32.f32 %0, %1;" : "=r"(u) : "f"(f));
    return u;
}

__device__ __forceinline__ void mma_tf32(float* d, const uint32_t* a, const uint32_t* b) {
    asm volatile(
        "mma.sync.aligned.m16n8k8.row.col.f32.tf32.tf32.f32 "
        "{%0,%1,%2,%3}, {%4,%5,%6,%7}, {%8,%9}, {%0,%1,%2,%3};"
        : "+f"(d[0]), "+f"(d[1]), "+f"(d[2]), "+f"(d[3])
        : "r"(a[0]), "r"(a[1]), "r"(a[2]), "r"(a[3]), "r"(b[0]), "r"(b[1]));
}

__device__ __forceinline__ void lse_merge(float& m, float& s, float om, float os) {
    float M = fmaxf(m, om);
    s = s * expf(m - M) + os * expf(om - M);
    m = M;
}

__device__ __forceinline__ float sigmf(float v) { return 1.f / (1.f + expf(-v)); }

// ---------------- generic tf32 GEMM: C[M,N] = A[M,K] * B[N,K]^T ----------------
template <int BM, bool DUAL, bool FUSE_LSE, bool HALF>
__global__ void __launch_bounds__(256)
k_tf32_gemm(const float* __restrict__ A0, const float* __restrict__ B0, void* __restrict__ C0p,
            const float* __restrict__ A1, const float* __restrict__ B1, void* __restrict__ C1p,
            int M, int N, int K, int ldc, float2* __restrict__ part, int pstride) {
    const float* A = (DUAL && blockIdx.z) ? A1 : A0;
    const float* B = (DUAL && blockIdx.z) ? B1 : B0;
    void*      Cp = (DUAL && blockIdx.z) ? C1p : C0p;

    constexpr int MF = BM / 32;
    constexpr int PA = BM / 32;
    __shared__ uint32_t As[BM * 32];
    __shared__ uint32_t Bs[128 * 32];

    int tid = threadIdx.x;
    int lane = tid & 31, wid = tid >> 5;
    int tig = lane & 3, grp4 = lane >> 2;
    int wm = (wid & 1) * (BM / 2);
    int wn = (wid >> 1) * 32;
    int m0 = blockIdx.y * BM, n0 = blockIdx.x * 128;

    float acc[MF][4][4];
#pragma unroll
    for (int i = 0; i < MF; i++)
#pragma unroll
        for (int j = 0; j < 4; j++)
#pragma unroll
            for (int k = 0; k < 4; k++) acc[i][j][k] = 0.f;

    int aRow[PA], aGrp[PA], aOk[PA];
    const float* aPtr[PA];
    int bRow[4], bGrp[4], bOk[4];
    const float* bPtr[4];
#pragma unroll
    for (int p = 0; p < PA; p++) {
        int idx = tid + p * 256;
        aRow[p] = idx >> 3; aGrp[p] = idx & 7;
        int gm = m0 + aRow[p];
        aOk[p] = (gm < M);
        aPtr[p] = A + (size_t)(aOk[p] ? gm : 0) * K + aGrp[p] * 4;
    }
#pragma unroll
    for (int p = 0; p < 4; p++) {
        int idx = tid + p * 256;
        bRow[p] = idx >> 3; bGrp[p] = idx & 7;
        int gn = n0 + bRow[p];
        bOk[p] = (gn < N);
        bPtr[p] = B + (size_t)(bOk[p] ? gn : 0) * K + bGrp[p] * 4;
    }

    const float4 z4 = make_float4(0.f, 0.f, 0.f, 0.f);
    float4 pa[PA], pb[4];
#pragma unroll
    for (int p = 0; p < PA; p++) pa[p] = aOk[p] ? *(const float4*)(aPtr[p]) : z4;
#pragma unroll
    for (int p = 0; p < 4; p++)  pb[p] = bOk[p] ? *(const float4*)(bPtr[p]) : z4;

    int nk = K >> 5;
    for (int ks = 0; ks < nk; ks++) {
#pragma unroll
        for (int p = 0; p < PA; p++) {
            uint32_t* d = &As[aRow[p] * 32 + ((aGrp[p] ^ (aRow[p] & 7)) << 2)];
            *(uint4*)d = make_uint4(f2tf(pa[p].x), f2tf(pa[p].y), f2tf(pa[p].z), f2tf(pa[p].w));
        }
#pragma unroll
        for (int p = 0; p < 4; p++) {
            uint32_t* d = &Bs[bRow[p] * 32 + ((bGrp[p] ^ (bRow[p] & 7)) << 2)];
            *(uint4*)d = make_uint4(f2tf(pb[p].x), f2tf(pb[p].y), f2tf(pb[p].z), f2tf(pb[p].w));
        }
        __syncthreads();

        if (ks + 1 < nk) {
            int off = (ks + 1) * 32;
#pragma unroll
            for (int p = 0; p < PA; p++) pa[p] = aOk[p] ? *(const float4*)(aPtr[p] + off) : z4;
#pragma unroll
            for (int p = 0; p < 4; p++)  pb[p] = bOk[p] ? *(const float4*)(bPtr[p] + off) : z4;
        }

#pragma unroll
        for (int kk = 0; kk < 4; kk++) {
            int g0 = kk * 2, g1 = kk * 2 + 1;
            uint32_t a[MF][4], b[4][2];
#pragma unroll
            for (int mf = 0; mf < MF; mf++) {
                int r = wm + mf * 16 + grp4;
                int base = r * 32 + tig;
                int s0 = (g0 ^ (r & 7)) << 2;
                int s1 = (g1 ^ (r & 7)) << 2;
                a[mf][0] = As[base + s0];
                a[mf][1] = As[base + 256 + s0];
                a[mf][2] = As[base + s1];
                a[mf][3] = As[base + 256 + s1];
            }
#pragma unroll
            for (int nf = 0; nf < 4; nf++) {
                int rn = wn + nf * 8 + grp4;
                int base = rn * 32 + tig;
                b[nf][0] = Bs[base + ((g0 ^ (rn & 7)) << 2)];
                b[nf][1] = Bs[base + ((g1 ^ (rn & 7)) << 2)];
            }
#pragma unroll
            for (int mf = 0; mf < MF; mf++)
#pragma unroll
                for (int nf = 0; nf < 4; nf++)
                    mma_tf32(acc[mf][nf], a[mf], b[nf]);
        }
        __syncthreads();
    }

#pragma unroll
    for (int mf = 0; mf < MF; mf++) {
        int r0 = m0 + wm + mf * 16 + grp4;
        int r1 = r0 + 8;
#pragma unroll
        for (int nf = 0; nf < 4; nf++) {
            int cb = n0 + wn + nf * 8 + 2 * tig;
            if (cb >= N) continue;
            if (HALF) {
                __half* C = (__half*)Cp;
                if (r0 < M) *(__half2*)(C + (size_t)r0 * ldc + cb) =
                    __floats2half2_rn(acc[mf][nf][0], acc[mf][nf][1]);
                if (r1 < M) *(__half2*)(C + (size_t)r1 * ldc + cb) =
                    __floats2half2_rn(acc[mf][nf][2], acc[mf][nf][3]);
            } else {
                float* C = (float*)Cp;
                if (r0 < M) *(float2*)(C + (size_t)r0 * ldc + cb) = make_float2(acc[mf][nf][0], acc[mf][nf][1]);
                if (r1 < M) *(float2*)(C + (size_t)r1 * ldc + cb) = make_float2(acc[mf][nf][2], acc[mf][nf][3]);
            }
        }
    }

    if (FUSE_LSE) {
        int xc = blockIdx.x * 4 + (wid >> 1);
#pragma unroll
        for (int mf = 0; mf < MF; mf++) {
#pragma unroll
            for (int half = 0; half < 2; half++) {
                int row = m0 + wm + mf * 16 + grp4 + half * 8;
                float mx = -1e30f;
#pragma unroll
                for (int nf = 0; nf < 4; nf++) {
                    int cb = n0 + wn + nf * 8 + 2 * tig;
                    if (cb < N)     mx = fmaxf(mx, acc[mf][nf][half * 2]);
                    if (cb + 1 < N) mx = fmaxf(mx, acc[mf][nf][half * 2 + 1]);
                }
                mx = fmaxf(mx, __shfl_xor_sync(0xffffffffu, mx, 1));
                mx = fmaxf(mx, __shfl_xor_sync(0xffffffffu, mx, 2));
                float s = 0.f;
#pragma unroll
                for (int nf = 0; nf < 4; nf++) {
                    int cb = n0 + wn + nf * 8 + 2 * tig;
                    if (cb < N)     s += expf(acc[mf][nf][half * 2]     - mx);
                    if (cb + 1 < N) s += expf(acc[mf][nf][half * 2 + 1] - mx);
                }
                s += __shfl_xor_sync(0xffffffffu, s, 1);
                s += __shfl_xor_sync(0xffffffffu, s, 2);
                if (tig == 0 && row < M)
                    part[(size_t)row * pstride + xc] = make_float2(mx, s);
            }
        }
    }
}

// ---------------- tf32 einsum, small tiles for full-chip occupancy ----------------
__global__ void __launch_bounds__(256)
k_gt_tf32(const float* __restrict__ G, int l, const float* __restrict__ X, float* __restrict__ C) {
    int b  = blockIdx.z;
    int i0 = blockIdx.y * 32;
    int d0 = blockIdx.x * 64;
    const float* Gb = G + ((size_t)b * Ll + l) * Tt * Tt;
    const float* Xb = X + (size_t)b * Tt * Ee;

    __shared__ uint32_t As[32 * 32];
    __shared__ uint32_t Bs[64 * 32];

    int tid = threadIdx.x;
    int lane = tid & 31, wid = tid >> 5;
    int tig = lane & 3, grp4 = lane >> 2;
    int wm = (wid & 1) * 16;
    int wn = (wid >> 1) * 16;

    float acc[2][4];
#pragma unroll
    for (int j = 0; j < 2; j++)
#pragma unroll
        for (int k = 0; k < 4; k++) acc[j][k] = 0.f;

    int jlA = tid & 31, i4A = tid >> 5;
    int jlB[2], d4B[2];
#pragma unroll
    for (int p = 0; p < 2; p++) { int idx = tid + p * 256; jlB[p] = idx & 31; d4B[p] = idx >> 5; }

    float4 ga, xa[2];
    ga = *(const float4*)(Gb + (size_t)jlA * Tt + i0 + i4A * 4);
#pragma unroll
    for (int p = 0; p < 2; p++) xa[p] = *(const float4*)(Xb + (size_t)jlB[p] * Ee + d0 + d4B[p] * 4);

    for (int ks = 0; ks < 4; ks++) {
        {
            int grp = jlA >> 2, t = jlA & 3;
            float gv[4] = {ga.x, ga.y, ga.z, ga.w};
#pragma unroll
            for (int q = 0; q < 4; q++) {
                int r = i4A * 4 + q;
                As[r * 32 + ((grp ^ (r & 7)) << 2) + t] = f2tf(gv[q]);
            }
        }
#pragma unroll
        for (int p = 0; p < 2; p++) {
            int grp = jlB[p] >> 2, t = jlB[p] & 3;
            float xf[4] = {xa[p].x, xa[p].y, xa[p].z, xa[p].w};
#pragma unroll
            for (int q = 0; q < 4; q++) {
                int r = d4B[p] * 4 + q;
                Bs[r * 32 + ((grp ^ (r & 7)) << 2) + t] = f2tf(xf[q]);
            }
        }
        __syncthreads();

        if (ks < 3) {
            int j0 = (ks + 1) * 32;
            ga = *(const float4*)(Gb + (size_t)(j0 + jlA) * Tt + i0 + i4A * 4);
#pragma unroll
            for (int p = 0; p < 2; p++) xa[p] = *(const float4*)(Xb + (size_t)(j0 + jlB[p]) * Ee + d0 + d4B[p] * 4);
        }

#pragma unroll
        for (int kk = 0; kk < 4; kk++) {
            int g0 = kk * 2, g1 = kk * 2 + 1;
            uint32_t a[4], bb[2][2];
            {
                int r = wm + grp4;
                int base = r * 32 + tig;
                int s0 = (g0 ^ (r & 7)) << 2;
                int s1 = (g1 ^ (r & 7)) << 2;
                a[0] = As[base + s0];
                a[1] = As[base + 256 + s0];
                a[2] = As[base + s1];
                a[3] = As[base + 256 + s1];
            }
#pragma unroll
            for (int nf = 0; nf < 2; nf++) {
                int rn = wn + nf * 8 + grp4;
                int base = rn * 32 + tig;
                bb[nf][0] = Bs[base + ((g0 ^ (rn & 7)) << 2)];
                bb[nf][1] = Bs[base + ((g1 ^ (rn & 7)) << 2)];
            }
#pragma unroll
            for (int nf = 0; nf < 2; nf++)
                mma_tf32(acc[nf], a, bb[nf]);
        }
        __syncthreads();
    }

    float* Cb = C + (size_t)b * Tt * Ee;
    int r0 = i0 + wm + grp4;
    int r1 = r0 + 8;
#pragma unroll
    for (int nf = 0; nf < 2; nf++) {
        int cb = d0 + wn + nf * 8 + 2 * tig;
        *(float2*)(Cb + (size_t)r0 * Ee + cb) = make_float2(acc[nf][0], acc[nf][1]);
        *(float2*)(Cb + (size_t)r1 * Ee + cb) = make_float2(acc[nf][2], acc[nf][3]);
    }
}

// combine per-row partials -> lse[row]
__global__ void k_lse_combine(const float2* __restrict__ part, int cnt, float* __restrict__ out) {
    int row = blockIdx.x;
    float mx = -1e30f, s = 0.f;
    for (int i = threadIdx.x; i < cnt; i += blockDim.x) {
        float2 p = part[(size_t)row * cnt + i];
        lse_merge(mx, s, p.x, p.y);
    }
#pragma unroll
    for (int o = 16; o; o >>= 1) {
        float om = __shfl_xor_sync(0xffffffffu, mx, o);
        float os = __shfl_xor_sync(0xffffffffu, s, o);
        lse_merge(mx, s, om, os);
    }
    __shared__ float rm[4], rs[4];
    int lane = threadIdx.x & 31, w = threadIdx.x >> 5;
    if (lane == 0) { rm[w] = mx; rs[w] = s; }
    __syncthreads();
    if (threadIdx.x == 0) {
        float M = rm[0], S = rs[0];
        for (int i = 1; i < (blockDim.x >> 5); i++) lse_merge(M, S, rm[i], rs[i]);
        out[row] = M + logf(S);
    }
}

// ---------------- other kernels ----------------
__global__ void k_embed(const int* __restrict__ x, const float* __restrict__ emb,
                        float* __restrict__ embedded, float* __restrict__ inputf) {
    int r = blockIdx.x;
    int tok = x[r];
    float4 v = ((const float4*)(emb + (size_t)tok * Ee))[threadIdx.x];
    ((float4*)(embedded + (size_t)r * Ee))[threadIdx.x] = v;
    ((float4*)(inputf   + (size_t)r * Ee))[threadIdx.x] = v;
}

__global__ void k_gru_combine(const float* __restrict__ gi, const float* __restrict__ gh,
                              const float* __restrict__ b_ih, const float* __restrict__ b_hh,
                              const float* __restrict__ h_in, float* __restrict__ h_out,
                              int N, float* __restrict__ out2,
                              const int* __restrict__ lengths, int dstep) {
    int idx = blockIdx.x * blockDim.x + threadIdx.x;
    if (idx >= N * Hh) return;
    int n = idx / Hh, k = idx - n * Hh;
    size_t base = (size_t)n * G3H;
    float ir = gi[base + k]           + b_ih[k];
    float iz = gi[base + Hh + k]      + b_ih[Hh + k];
    float in_ = gi[base + 2 * Hh + k] + b_ih[2 * Hh + k];
    float hr = gh[base + k]           + b_hh[k];
    float hz = gh[base + Hh + k]      + b_hh[Hh + k];
    float hn = gh[base + 2 * Hh + k]  + b_hh[2 * Hh + k];
    float r = sigmf(ir + hr);
    float z = sigmf(iz + hz);
    float nn = tanhf(in_ + r * hn);
    float val = (1.f - z) * nn + z * h_in[idx];
    h_out[idx] = val;
    if (out2) {
        int b = n / NTt, t = n - b * NTt;
        float v2 = (t + dstep < lengths[b]) ? val : 0.f;
        out2[idx] = v2;
    }
}

__global__ void k_wingather(const float* __restrict__ embedded, const int* __restrict__ lengths,
                            float* __restrict__ wins) {
    int r = blockIdx.x;
    int d = r & 3;
    int bt = r >> 2;
    int b = bt / NTt, t = bt - b * NTt;
    int idx = (t == 0 && d == 0) ? (lengths[b] - 1) : (t + d - 1);
    const float4* src = (const float4*)(embedded + ((size_t)b * Tt + idx) * Ee);
    float4* dst = (float4*)(wins + ((size_t)d * NDEC + bt) * Ee);
    dst[threadIdx.x] = src[threadIdx.x];
}

__global__ void k_h0(const float* __restrict__ inputf, float* __restrict__ h) {
    int n = blockIdx.x;
    int b = n / NTt, t = n - b * NTt;
    ((float4*)(h + (size_t)n * Hh))[threadIdx.x] =
        ((const float4*)(inputf + ((size_t)b * Tt + t) * Ee))[threadIdx.x];
}

// Region write: out row R (= bt*4+d) reads permuted scratch row sr = d*NDEC + bt.
__global__ void k_write_region(const __half* __restrict__ src, int srcStride,
                               int colStart, int width,
                               const __half* __restrict__ hl, int headcol,
                               const float* __restrict__ lseh, const float* __restrict__ lse2,
                               const int* __restrict__ lengths, float* __restrict__ out) {
    int row = blockIdx.y;
    int v4 = blockIdx.x * blockDim.x + threadIdx.x;
    if (v4 >= (width >> 2)) return;
    int d = row & 3;
    int bt = row >> 2;
    int sr = d * NDEC + bt;
    int b = bt / NTt, t = bt - b * NTt;
    float4* o = (float4*)(out + (size_t)row * Vv + colStart) + v4;
    if (t >= __ldg(lengths + b)) { __stcs(o, make_float4(0.f, 0.f, 0.f, 0.f)); return; }
    float c = -__ldg(lseh + sr);
    if (lse2)
        c += __half2float(__ldg(hl + (size_t)sr * HLDC + headcol)) - __ldg(lse2 + sr);
    const __half* s = src + (size_t)sr * srcStride + v4 * 4;
    float2 f01 = __half22float2(__ldg((const __half2*)(s)));
    float2 f23 = __half22float2(__ldg((const __half2*)(s + 2)));
    __stcs(o, make_float4(f01.x + c, f01.y + c, f23.x + c, f23.y + c));
}

// Chunked region write: rows indexed by scratch row sr = srBase + blockIdx.y.
__global__ void k_write_chunk(const __half* __restrict__ src, int srcStride,
                              int colStart, int width,
                              const __half* __restrict__ hl, int headcol,
                              const float* __restrict__ lseh, const float* __restrict__ lse2,
                              const int* __restrict__ lengths, float* __restrict__ out,
                              int srBase) {
    int sr = srBase + blockIdx.y;
    int v4 = blockIdx.x * blockDim.x + threadIdx.x;
    if (v4 >= (width >> 2)) return;
    int d = sr / NDEC;
    int bt = sr - d * NDEC;
    int R = bt * 4 + d;
    int b = bt / NTt, t = bt - b * NTt;
    float4* o = (float4*)(out + (size_t)R * Vv + colStart) + v4;
    if (t >= __ldg(lengths + b)) { __stcs(o, make_float4(0.f, 0.f, 0.f, 0.f)); return; }
    float c = __half2float(__ldg(hl + (size_t)sr * HLDC + headcol))
              - __ldg(lseh + sr) - __ldg(lse2 + sr);
    const __half* s = src + (size_t)sr * srcStride + v4 * 4;
    float2 f01 = __half22float2(__ldg((const __half2*)(s)));
    float2 f23 = __half22float2(__ldg((const __half2*)(s + 2)));
    __stcs(o, make_float4(f01.x + c, f01.y + c, f23.x + c, f23.y + c));
}

// ---------------- host orchestration ----------------
extern "C" void kernel_launch(void* const* d_in, const int* in_sizes, int n_in,
                              void* d_out, int out_size) {
    const int*   x        = (const int*)d_in[0];
    const int*   lengths  = (const int*)d_in[1];
    const float* G        = (const float*)d_in[2];
    const float* emb      = (const float*)d_in[3];
    const float* enc_w_ih = (const float*)d_in[4];
    const float* enc_w_hh = (const float*)d_in[5];
    const float* enc_b_ih = (const float*)d_in[6];
    const float* enc_b_hh = (const float*)d_in[7];
    const float* dec_w_ih = (const float*)d_in[8];
    const float* dec_w_hh = (const float*)d_in[9];
    const float* dec_b_ih = (const float*)d_in[10];
    const float* dec_b_hh = (const float*)d_in[11];
    const float* head_w   = (const float*)d_in[12];
    const float* t0_proj  = (const float*)d_in[13];
    const float* t0_out   = (const float*)d_in[14];
    const float* t1_proj  = (const float*)d_in[15];
    const float* t1_out   = (const float*)d_in[16];
    float* out = (float*)d_out;

    float *embedded, *inputf, *wgt, *egi, *gi, *gh, *wins, *h, *hs, *z0, *z1;
    float *lh, *l0, *l1;
    __half *hl, *t0l, *t1l;
    float2 *ph, *p0, *p1;
    cudaGetSymbolAddress((void**)&embedded, g_embedded);
    cudaGetSymbolAddress((void**)&inputf,   g_inputf);
    cudaGetSymbolAddress((void**)&wgt,      g_wgt);
    cudaGetSymbolAddress((void**)&egi,      g_egi);
    cudaGetSymbolAddress((void**)&gi,       g_gi);
    cudaGetSymbolAddress((void**)&gh,       g_gh);
    cudaGetSymbolAddress((void**)&wins,     g_wins);
    cudaGetSymbolAddress((void**)&h,        g_h);
    cudaGetSymbolAddress((void**)&hs,       g_hs);
    cudaGetSymbolAddress((void**)&z0,       g_z0);
    cudaGetSymbolAddress((void**)&z1,       g_z1);
    cudaGetSymbolAddress((void**)&hl,       g_headlog);
    cudaGetSymbolAddress((void**)&t0l,      g_t0log);
    cudaGetSymbolAddress((void**)&t1l,      g_t1log);
    cudaGetSymbolAddress((void**)&lh,       g_lseh);
    cudaGetSymbolAddress((void**)&l0,       g_lse0);
    cudaGetSymbolAddress((void**)&l1,       g_lse1);
    cudaGetSymbolAddress((void**)&ph,       g_parth);
    cudaGetSymbolAddress((void**)&p0,       g_part0);
    cudaGetSymbolAddress((void**)&p1,       g_part1);

    static cudaStream_t s2 = 0, s3 = 0, s4 = 0;
    static cudaEvent_t eEmb = 0, eGi = 0, eHs2 = 0, eHs3 = 0;
    static cudaEvent_t eStep[4] = {0, 0, 0, 0};
    static cudaEvent_t eT1g[4] = {0, 0, 0, 0};
    static cudaEvent_t eHead2 = 0, eW2 = 0, eW3 = 0, eW4 = 0;
    if (!s2) {
        cudaStreamCreateWithFlags(&s2, cudaStreamNonBlocking);
        cudaStreamCreateWithFlags(&s3, cudaStreamNonBlocking);
        cudaStreamCreateWithFlags(&s4, cudaStreamNonBlocking);
        cudaEventCreateWithFlags(&eEmb,   cudaEventDisableTiming);
        cudaEventCreateWithFlags(&eGi,    cudaEventDisableTiming);
        cudaEventCreateWithFlags(&eHs2,   cudaEventDisableTiming);
        cudaEventCreateWithFlags(&eHs3,   cudaEventDisableTiming);
        for (int d = 0; d < 4; d++) cudaEventCreateWithFlags(&eStep[d], cudaEventDisableTiming);
        for (int d = 0; d < 4; d++) cudaEventCreateWithFlags(&eT1g[d], cudaEventDisableTiming);
        cudaEventCreateWithFlags(&eHead2, cudaEventDisableTiming);
        cudaEventCreateWithFlags(&eW2,    cudaEventDisableTiming);
        cudaEventCreateWithFlags(&eW3,    cudaEventDisableTiming);
        cudaEventCreateWithFlags(&eW4,    cudaEventDisableTiming);
    }

    // 1) embedding (main)
    k_embed<<<NENC, 128>>>(x, emb, embedded, inputf);
    cudaEventRecord(eEmb, 0);

    // side stream s2: window gather + decoder-gi GEMM, concurrent with encoder
    cudaStreamWaitEvent(s2, eEmb, 0);
    k_wingather<<<NROW, 128, 0, s2>>>(embedded, lengths, wins);
    k_tf32_gemm<128, false, false, false><<<dim3(G3H / 128, (NROW + 127) / 128), 256, 0, s2>>>(
        wins, dec_w_ih, gi, 0, 0, 0, NROW, G3H, Ee, G3H, (float2*)0, 0);
    cudaEventRecord(eGi, s2);

    // main: encoder layers
    for (int l = 0; l < Ll; l++) {
        k_gt_tf32<<<dim3(Ee / 64, Tt / 32, Bb), 256>>>(G, l, inputf, wgt);
        dim3 gA(G3H / 128, NENC / 32, 2);
        k_tf32_gemm<32, true, false, false><<<gA, 256>>>(
            wgt,    enc_w_ih + (size_t)l * G3H * Hh, egi,
            inputf, enc_w_hh + (size_t)l * G3H * Hh, gh,
            NENC, G3H, Hh, G3H, (float2*)0, 0);
        k_gru_combine<<<(NENC * Hh + 255) / 256, 256>>>(egi, gh, enc_b_ih + l * G3H, enc_b_hh + l * G3H,
                                                        inputf, inputf, NENC, (float*)0, (int*)0, 0);
    }
    k_h0<<<NDEC, 128>>>(inputf, h);

    // join gi
    cudaStreamWaitEvent(0, eGi, 0);

    // decoder: 4 sequential GRU steps; head GEMM chunk per step on s4 (R13 form)
    for (int d = 0; d < Dd; d++) {
        k_tf32_gemm<32, false, false, false><<<dim3(G3H / 128, (NDEC + 31) / 32), 256>>>(
            h, dec_w_hh, gh, 0, 0, 0, NDEC, G3H, Hh, G3H, (float2*)0, 0);
        k_gru_combine<<<(NDEC * Hh + 255) / 256, 256>>>(
            gi + (size_t)d * NDEC * G3H, gh, dec_b_ih, dec_b_hh,
            h, h, NDEC, hs + (size_t)d * NDEC * Hh, lengths, d);
        cudaEventRecord(eStep[d], 0);
        cudaStreamWaitEvent(s4, eStep[d], 0);
        k_tf32_gemm<64, false, true, true><<<dim3(16, (NDEC + 63) / 64), 256, 0, s4>>>(
            hs + (size_t)d * NDEC * Hh, head_w, hl + (size_t)d * NDEC * HLDC,
            0, 0, 0, NDEC, 2002, Hh, HLDC, ph + (size_t)d * NDEC * PH, PH);
    }
    cudaEventRecord(eHs2, 0);
    cudaEventRecord(eHs3, 0);

    // s4: head LSE combine + head-region write
    k_lse_combine<<<NROW, 128, 0, s4>>>(ph, PH, lh);
    cudaEventRecord(eHead2, s4);
    k_write_region<<<dim3(2, NROW), 256, 0, s4>>>(hl, HLDC, 0, C0c, hl, 0, lh, (float*)0, lengths, out);

    // s2: t0 chain (R13 form)
    cudaStreamWaitEvent(s2, eHs2, 0);
    k_tf32_gemm<128, false, false, false><<<dim3(1, (NROW + 127) / 128), 256, 0, s2>>>(
        hs, t0_proj, z0, 0, 0, 0, NROW, 128, Hh, 128, (float2*)0, 0);
    k_tf32_gemm<128, false, true, true><<<dim3(63, (NROW + 127) / 128), 256, 0, s2>>>(
        z0, t0_out, t0l, 0, 0, 0, NROW, W0, 128, W0, p0, P0);
    k_lse_combine<<<NROW, 128, 0, s2>>>(p0, P0, l0);
    cudaStreamWaitEvent(s2, eHead2, 0);
    k_write_region<<<dim3(8, NROW), 256, 0, s2>>>(t0l, W0, C0c, W0, hl, C0c, lh, l0, lengths, out);
    cudaEventRecord(eW2, s2);

    // s3: t1 proj, then logits GEMM in 4 row-chunks of 500 (pipelined with s4 writes)
    cudaStreamWaitEvent(s3, eHs3, 0);
    k_tf32_gemm<128, false, false, false><<<dim3(1, (NROW + 127) / 128), 256, 0, s3>>>(
        hs, t1_proj, z1, 0, 0, 0, NROW, 32, Hh, 32, (float2*)0, 0);
    for (int c = 0; c < 4; c++) {
        k_tf32_gemm<128, false, true, true><<<dim3(172, (NDEC + 127) / 128), 256, 0, s3>>>(
            z1 + (size_t)c * NDEC * 32, t1_out, t1l + (size_t)c * NDEC * W1,
            0, 0, 0, NDEC, W1, 32, W1, p1 + (size_t)c * NDEC * P1, P1);
        cudaEventRecord(eT1g[c], s3);
    }
    cudaEventRecord(eW3, s3);

    // s4 (after head write): per-chunk t1 combine + write, overlapping s3's next GEMM chunk
    for (int c = 0; c < 4; c++) {
        cudaStreamWaitEvent(s4, eT1g[c], 0);
        k_lse_combine<<<NDEC, 128, 0, s4>>>(p1 + (size_t)c * NDEC * P1, P1, l1 + c * NDEC);
        k_write_chunk<<<dim3(22, NDEC), 256, 0, s4>>>(
            t1l, W1, C1c, W1, hl, C0c + 1, lh, l1, lengths, out, c * NDEC);
    }
    cudaEventRecord(eW4, s4);

    // join everything back to main
    cudaStreamWaitEvent(0, eW2, 0);
    cudaStreamWaitEvent(0, eW3, 0);
    cudaStreamWaitEvent(0, eW4, 0);
}

// round 17
// speedup vs baseline: 1.2617x; 1.0246x over previous
#include <cuda_runtime.h>
#include <cuda_fp16.h>
#include <math.h>
#include <stdint.h>

// Problem constants
#define Vv    32000
#define Ee    512
#define Hh    512
#define Tt    128
#define Bb    4
#define Dd    4
#define Ll    2
#define C0c   2000
#define C1c   10000
#define NTt   125            // T - D + 1
#define NROW  2000           // B*NT*D
#define NDEC  500            // B*NT
#define NENC  512            // B*T
#define G3H   1536           // 3*H
#define HLDC  2004           // padded head-logit row stride
#define W0    8000           // C1-C0
#define W1    22000          // V-C1

// partial-LSE strides
#define PH    64
#define P0    252
#define P1    688

// ---------------- device scratch ----------------
// hs layout: [d][NDEC][H] (step-major). Output row R = bt*4+d -> scratch row sr = d*NDEC+bt.
__device__ float g_embedded[NENC * Ee];
__device__ float g_inputf[NENC * Ee];
__device__ float g_wgt[NENC * Ee];
__device__ float g_egi[NENC * G3H];
__device__ float g_gi[NROW * G3H];
__device__ float g_gh[NENC * G3H];
__device__ float g_wins[Dd * NDEC * Ee];
__device__ float g_h[NDEC * Hh];
__device__ float g_hs[NROW * Hh];
__device__ float g_z0[NROW * 128];
__device__ float g_z1[NROW * 32];
__device__ __half g_headlog[NROW * HLDC];
__device__ __half g_t0log[(size_t)NROW * W0];
__device__ __half g_t1log[(size_t)NROW * W1];
__device__ float g_lseh[NROW];
__device__ float g_lse0[NROW];
__device__ float g_lse1[NROW];
__device__ float2 g_parth[NROW * PH];
__device__ float2 g_part0[NROW * P0];
__device__ float2 g_part1[NROW * P1];

// ---------------- tf32 helpers ----------------
__device__ __forceinline__ uint32_t f2tf(float f) {
    uint32_t u;
    asm("cvt.rna.tf32.f32 %0, %1;" : "=r"(u) : "f"(f));
    return u;
}

__device__ __forceinline__ void mma_tf32(float* d, const uint32_t* a, const uint32_t* b) {
    asm volatile(
        "mma.sync.aligned.m16n8k8.row.col.f32.tf32.tf32.f32 "
        "{%0,%1,%2,%3}, {%4,%5,%6,%7}, {%8,%9}, {%0,%1,%2,%3};"
        : "+f"(d[0]), "+f"(d[1]), "+f"(d[2]), "+f"(d[3])
        : "r"(a[0]), "r"(a[1]), "r"(a[2]), "r"(a[3]), "r"(b[0]), "r"(b[1]));
}

__device__ __forceinline__ void lse_merge(float& m, float& s, float om, float os) {
    float M = fmaxf(m, om);
    s = s * expf(m - M) + os * expf(om - M);
    m = M;
}

__device__ __forceinline__ float sigmf(float v) { return 1.f / (1.f + expf(-v)); }

// ---------------- generic tf32 GEMM: C[M,N] = A[M,K] * B[N,K]^T ----------------
template <int BM, bool DUAL, bool FUSE_LSE, bool HALF>
__global__ void __launch_bounds__(256)
k_tf32_gemm(const float* __restrict__ A0, const float* __restrict__ B0, void* __restrict__ C0p,
            const float* __restrict__ A1, const float* __restrict__ B1, void* __restrict__ C1p,
            int M, int N, int K, int ldc, float2* __restrict__ part, int pstride) {
    const float* A = (DUAL && blockIdx.z) ? A1 : A0;
    const float* B = (DUAL && blockIdx.z) ? B1 : B0;
    void*      Cp = (DUAL && blockIdx.z) ? C1p : C0p;

    constexpr int MF = BM / 32;
    constexpr int PA = BM / 32;
    __shared__ uint32_t As[BM * 32];
    __shared__ uint32_t Bs[128 * 32];

    int tid = threadIdx.x;
    int lane = tid & 31, wid = tid >> 5;
    int tig = lane & 3, grp4 = lane >> 2;
    int wm = (wid & 1) * (BM / 2);
    int wn = (wid >> 1) * 32;
    int m0 = blockIdx.y * BM, n0 = blockIdx.x * 128;

    float acc[MF][4][4];
#pragma unroll
    for (int i = 0; i < MF; i++)
#pragma unroll
        for (int j = 0; j < 4; j++)
#pragma unroll
            for (int k = 0; k < 4; k++) acc[i][j][k] = 0.f;

    int aRow[PA], aGrp[PA], aOk[PA];
    const float* aPtr[PA];
    int bRow[4], bGrp[4], bOk[4];
    const float* bPtr[4];
#pragma unroll
    for (int p = 0; p < PA; p++) {
        int idx = tid + p * 256;
        aRow[p] = idx >> 3; aGrp[p] = idx & 7;
        int gm = m0 + aRow[p];
        aOk[p] = (gm < M);
        aPtr[p] = A + (size_t)(aOk[p] ? gm : 0) * K + aGrp[p] * 4;
    }
#pragma unroll
    for (int p = 0; p < 4; p++) {
        int idx = tid + p * 256;
        bRow[p] = idx >> 3; bGrp[p] = idx & 7;
        int gn = n0 + bRow[p];
        bOk[p] = (gn < N);
        bPtr[p] = B + (size_t)(bOk[p] ? gn : 0) * K + bGrp[p] * 4;
    }

    const float4 z4 = make_float4(0.f, 0.f, 0.f, 0.f);
    float4 pa[PA], pb[4];
#pragma unroll
    for (int p = 0; p < PA; p++) pa[p] = aOk[p] ? *(const float4*)(aPtr[p]) : z4;
#pragma unroll
    for (int p = 0; p < 4; p++)  pb[p] = bOk[p] ? *(const float4*)(bPtr[p]) : z4;

    int nk = K >> 5;
    for (int ks = 0; ks < nk; ks++) {
#pragma unroll
        for (int p = 0; p < PA; p++) {
            uint32_t* d = &As[aRow[p] * 32 + ((aGrp[p] ^ (aRow[p] & 7)) << 2)];
            *(uint4*)d = make_uint4(f2tf(pa[p].x), f2tf(pa[p].y), f2tf(pa[p].z), f2tf(pa[p].w));
        }
#pragma unroll
        for (int p = 0; p < 4; p++) {
            uint32_t* d = &Bs[bRow[p] * 32 + ((bGrp[p] ^ (bRow[p] & 7)) << 2)];
            *(uint4*)d = make_uint4(f2tf(pb[p].x), f2tf(pb[p].y), f2tf(pb[p].z), f2tf(pb[p].w));
        }
        __syncthreads();

        if (ks + 1 < nk) {
            int off = (ks + 1) * 32;
#pragma unroll
            for (int p = 0; p < PA; p++) pa[p] = aOk[p] ? *(const float4*)(aPtr[p] + off) : z4;
#pragma unroll
            for (int p = 0; p < 4; p++)  pb[p] = bOk[p] ? *(const float4*)(bPtr[p] + off) : z4;
        }

#pragma unroll
        for (int kk = 0; kk < 4; kk++) {
            int g0 = kk * 2, g1 = kk * 2 + 1;
            uint32_t a[MF][4], b[4][2];
#pragma unroll
            for (int mf = 0; mf < MF; mf++) {
                int r = wm + mf * 16 + grp4;
                int base = r * 32 + tig;
                int s0 = (g0 ^ (r & 7)) << 2;
                int s1 = (g1 ^ (r & 7)) << 2;
                a[mf][0] = As[base + s0];
                a[mf][1] = As[base + 256 + s0];
                a[mf][2] = As[base + s1];
                a[mf][3] = As[base + 256 + s1];
            }
#pragma unroll
            for (int nf = 0; nf < 4; nf++) {
                int rn = wn + nf * 8 + grp4;
                int base = rn * 32 + tig;
                b[nf][0] = Bs[base + ((g0 ^ (rn & 7)) << 2)];
                b[nf][1] = Bs[base + ((g1 ^ (rn & 7)) << 2)];
            }
#pragma unroll
            for (int mf = 0; mf < MF; mf++)
#pragma unroll
                for (int nf = 0; nf < 4; nf++)
                    mma_tf32(acc[mf][nf], a[mf], b[nf]);
        }
        __syncthreads();
    }

#pragma unroll
    for (int mf = 0; mf < MF; mf++) {
        int r0 = m0 + wm + mf * 16 + grp4;
        int r1 = r0 + 8;
#pragma unroll
        for (int nf = 0; nf < 4; nf++) {
            int cb = n0 + wn + nf * 8 + 2 * tig;
            if (cb >= N) continue;
            if (HALF) {
                __half* C = (__half*)Cp;
                if (r0 < M) *(__half2*)(C + (size_t)r0 * ldc + cb) =
                    __floats2half2_rn(acc[mf][nf][0], acc[mf][nf][1]);
                if (r1 < M) *(__half2*)(C + (size_t)r1 * ldc + cb) =
                    __floats2half2_rn(acc[mf][nf][2], acc[mf][nf][3]);
            } else {
                float* C = (float*)Cp;
                if (r0 < M) *(float2*)(C + (size_t)r0 * ldc + cb) = make_float2(acc[mf][nf][0], acc[mf][nf][1]);
                if (r1 < M) *(float2*)(C + (size_t)r1 * ldc + cb) = make_float2(acc[mf][nf][2], acc[mf][nf][3]);
            }
        }
    }

    if (FUSE_LSE) {
        int xc = blockIdx.x * 4 + (wid >> 1);
#pragma unroll
        for (int mf = 0; mf < MF; mf++) {
#pragma unroll
            for (int half = 0; half < 2; half++) {
                int row = m0 + wm + mf * 16 + grp4 + half * 8;
                float mx = -1e30f;
#pragma unroll
                for (int nf = 0; nf < 4; nf++) {
                    int cb = n0 + wn + nf * 8 + 2 * tig;
                    if (cb < N)     mx = fmaxf(mx, acc[mf][nf][half * 2]);
                    if (cb + 1 < N) mx = fmaxf(mx, acc[mf][nf][half * 2 + 1]);
                }
                mx = fmaxf(mx, __shfl_xor_sync(0xffffffffu, mx, 1));
                mx = fmaxf(mx, __shfl_xor_sync(0xffffffffu, mx, 2));
                float s = 0.f;
#pragma unroll
                for (int nf = 0; nf < 4; nf++) {
                    int cb = n0 + wn + nf * 8 + 2 * tig;
                    if (cb < N)     s += expf(acc[mf][nf][half * 2]     - mx);
                    if (cb + 1 < N) s += expf(acc[mf][nf][half * 2 + 1] - mx);
                }
                s += __shfl_xor_sync(0xffffffffu, s, 1);
                s += __shfl_xor_sync(0xffffffffu, s, 2);
                if (tig == 0 && row < M)
                    part[(size_t)row * pstride + xc] = make_float2(mx, s);
            }
        }
    }
}

// ---------------- tf32 einsum, small tiles for full-chip occupancy ----------------
__global__ void __launch_bounds__(256)
k_gt_tf32(const float* __restrict__ G, int l, const float* __restrict__ X, float* __restrict__ C) {
    int b  = blockIdx.z;
    int i0 = blockIdx.y * 32;
    int d0 = blockIdx.x * 64;
    const float* Gb = G + ((size_t)b * Ll + l) * Tt * Tt;
    const float* Xb = X + (size_t)b * Tt * Ee;

    __shared__ uint32_t As[32 * 32];
    __shared__ uint32_t Bs[64 * 32];

    int tid = threadIdx.x;
    int lane = tid & 31, wid = tid >> 5;
    int tig = lane & 3, grp4 = lane >> 2;
    int wm = (wid & 1) * 16;
    int wn = (wid >> 1) * 16;

    float acc[2][4];
#pragma unroll
    for (int j = 0; j < 2; j++)
#pragma unroll
        for (int k = 0; k < 4; k++) acc[j][k] = 0.f;

    int jlA = tid & 31, i4A = tid >> 5;
    int jlB[2], d4B[2];
#pragma unroll
    for (int p = 0; p < 2; p++) { int idx = tid + p * 256; jlB[p] = idx & 31; d4B[p] = idx >> 5; }

    float4 ga, xa[2];
    ga = *(const float4*)(Gb + (size_t)jlA * Tt + i0 + i4A * 4);
#pragma unroll
    for (int p = 0; p < 2; p++) xa[p] = *(const float4*)(Xb + (size_t)jlB[p] * Ee + d0 + d4B[p] * 4);

    for (int ks = 0; ks < 4; ks++) {
        {
            int grp = jlA >> 2, t = jlA & 3;
            float gv[4] = {ga.x, ga.y, ga.z, ga.w};
#pragma unroll
            for (int q = 0; q < 4; q++) {
                int r = i4A * 4 + q;
                As[r * 32 + ((grp ^ (r & 7)) << 2) + t] = f2tf(gv[q]);
            }
        }
#pragma unroll
        for (int p = 0; p < 2; p++) {
            int grp = jlB[p] >> 2, t = jlB[p] & 3;
            float xf[4] = {xa[p].x, xa[p].y, xa[p].z, xa[p].w};
#pragma unroll
            for (int q = 0; q < 4; q++) {
                int r = d4B[p] * 4 + q;
                Bs[r * 32 + ((grp ^ (r & 7)) << 2) + t] = f2tf(xf[q]);
            }
        }
        __syncthreads();

        if (ks < 3) {
            int j0 = (ks + 1) * 32;
            ga = *(const float4*)(Gb + (size_t)(j0 + jlA) * Tt + i0 + i4A * 4);
#pragma unroll
            for (int p = 0; p < 2; p++) xa[p] = *(const float4*)(Xb + (size_t)(j0 + jlB[p]) * Ee + d0 + d4B[p] * 4);
        }

#pragma unroll
        for (int kk = 0; kk < 4; kk++) {
            int g0 = kk * 2, g1 = kk * 2 + 1;
            uint32_t a[4], bb[2][2];
            {
                int r = wm + grp4;
                int base = r * 32 + tig;
                int s0 = (g0 ^ (r & 7)) << 2;
                int s1 = (g1 ^ (r & 7)) << 2;
                a[0] = As[base + s0];
                a[1] = As[base + 256 + s0];
                a[2] = As[base + s1];
                a[3] = As[base + 256 + s1];
            }
#pragma unroll
            for (int nf = 0; nf < 2; nf++) {
                int rn = wn + nf * 8 + grp4;
                int base = rn * 32 + tig;
                bb[nf][0] = Bs[base + ((g0 ^ (rn & 7)) << 2)];
                bb[nf][1] = Bs[base + ((g1 ^ (rn & 7)) << 2)];
            }
#pragma unroll
            for (int nf = 0; nf < 2; nf++)
                mma_tf32(acc[nf], a, bb[nf]);
        }
        __syncthreads();
    }

    float* Cb = C + (size_t)b * Tt * Ee;
    int r0 = i0 + wm + grp4;
    int r1 = r0 + 8;
#pragma unroll
    for (int nf = 0; nf < 2; nf++) {
        int cb = d0 + wn + nf * 8 + 2 * tig;
        *(float2*)(Cb + (size_t)r0 * Ee + cb) = make_float2(acc[nf][0], acc[nf][1]);
        *(float2*)(Cb + (size_t)r1 * Ee + cb) = make_float2(acc[nf][2], acc[nf][3]);
    }
}

// combine per-row partials -> lse[row]
__global__ void k_lse_combine(const float2* __restrict__ part, int cnt, float* __restrict__ out) {
    int row = blockIdx.x;
    float mx = -1e30f, s = 0.f;
    for (int i = threadIdx.x; i < cnt; i += blockDim.x) {
        float2 p = part[(size_t)row * cnt + i];
        lse_merge(mx, s, p.x, p.y);
    }
#pragma unroll
    for (int o = 16; o; o >>= 1) {
        float om = __shfl_xor_sync(0xffffffffu, mx, o);
        float os = __shfl_xor_sync(0xffffffffu, s, o);
        lse_merge(mx, s, om, os);
    }
    __shared__ float rm[4], rs[4];
    int lane = threadIdx.x & 31, w = threadIdx.x >> 5;
    if (lane == 0) { rm[w] = mx; rs[w] = s; }
    __syncthreads();
    if (threadIdx.x == 0) {
        float M = rm[0], S = rs[0];
        for (int i = 1; i < (blockDim.x >> 5); i++) lse_merge(M, S, rm[i], rs[i]);
        out[row] = M + logf(S);
    }
}

// ---------------- other kernels ----------------
__global__ void k_embed(const int* __restrict__ x, const float* __restrict__ emb,
                        float* __restrict__ embedded, float* __restrict__ inputf) {
    int r = blockIdx.x;
    int tok = x[r];
    float4 v = ((const float4*)(emb + (size_t)tok * Ee))[threadIdx.x];
    ((float4*)(embedded + (size_t)r * Ee))[threadIdx.x] = v;
    ((float4*)(inputf   + (size_t)r * Ee))[threadIdx.x] = v;
}

__global__ void k_gru_combine(const float* __restrict__ gi, const float* __restrict__ gh,
                              const float* __restrict__ b_ih, const float* __restrict__ b_hh,
                              const float* __restrict__ h_in, float* __restrict__ h_out,
                              int N, float* __restrict__ out2,
                              const int* __restrict__ lengths, int dstep) {
    int idx = blockIdx.x * blockDim.x + threadIdx.x;
    if (idx >= N * Hh) return;
    int n = idx / Hh, k = idx - n * Hh;
    size_t base = (size_t)n * G3H;
    float ir = gi[base + k]           + b_ih[k];
    float iz = gi[base + Hh + k]      + b_ih[Hh + k];
    float in_ = gi[base + 2 * Hh + k] + b_ih[2 * Hh + k];
    float hr = gh[base + k]           + b_hh[k];
    float hz = gh[base + Hh + k]      + b_hh[Hh + k];
    float hn = gh[base + 2 * Hh + k]  + b_hh[2 * Hh + k];
    float r = sigmf(ir + hr);
    float z = sigmf(iz + hz);
    float nn = tanhf(in_ + r * hn);
    float val = (1.f - z) * nn + z * h_in[idx];
    h_out[idx] = val;
    if (out2) {
        int b = n / NTt, t = n - b * NTt;
        float v2 = (t + dstep < lengths[b]) ? val : 0.f;
        out2[idx] = v2;
    }
}

__global__ void k_wingather(const float* __restrict__ embedded, const int* __restrict__ lengths,
                            float* __restrict__ wins) {
    int r = blockIdx.x;
    int d = r & 3;
    int bt = r >> 2;
    int b = bt / NTt, t = bt - b * NTt;
    int idx = (t == 0 && d == 0) ? (lengths[b] - 1) : (t + d - 1);
    const float4* src = (const float4*)(embedded + ((size_t)b * Tt + idx) * Ee);
    float4* dst = (float4*)(wins + ((size_t)d * NDEC + bt) * Ee);
    dst[threadIdx.x] = src[threadIdx.x];
}

__global__ void k_h0(const float* __restrict__ inputf, float* __restrict__ h) {
    int n = blockIdx.x;
    int b = n / NTt, t = n - b * NTt;
    ((float4*)(h + (size_t)n * Hh))[threadIdx.x] =
        ((const float4*)(inputf + ((size_t)b * Tt + t) * Ee))[threadIdx.x];
}

// Region write: out row R (= bt*4+d) reads permuted scratch row sr = d*NDEC + bt.
__global__ void k_write_region(const __half* __restrict__ src, int srcStride,
                               int colStart, int width,
                               const __half* __restrict__ hl, int headcol,
                               const float* __restrict__ lseh, const float* __restrict__ lse2,
                               const int* __restrict__ lengths, float* __restrict__ out) {
    int row = blockIdx.y;
    int v4 = blockIdx.x * blockDim.x + threadIdx.x;
    if (v4 >= (width >> 2)) return;
    int d = row & 3;
    int bt = row >> 2;
    int sr = d * NDEC + bt;
    int b = bt / NTt, t = bt - b * NTt;
    float4* o = (float4*)(out + (size_t)row * Vv + colStart) + v4;
    if (t >= __ldg(lengths + b)) { __stcs(o, make_float4(0.f, 0.f, 0.f, 0.f)); return; }
    float c = -__ldg(lseh + sr);
    if (lse2)
        c += __half2float(__ldg(hl + (size_t)sr * HLDC + headcol)) - __ldg(lse2 + sr);
    const __half* s = src + (size_t)sr * srcStride + v4 * 4;
    float2 f01 = __half22float2(__ldg((const __half2*)(s)));
    float2 f23 = __half22float2(__ldg((const __half2*)(s + 2)));
    __stcs(o, make_float4(f01.x + c, f01.y + c, f23.x + c, f23.y + c));
}

// ---------------- host orchestration ----------------
extern "C" void kernel_launch(void* const* d_in, const int* in_sizes, int n_in,
                              void* d_out, int out_size) {
    const int*   x        = (const int*)d_in[0];
    const int*   lengths  = (const int*)d_in[1];
    const float* G        = (const float*)d_in[2];
    const float* emb      = (const float*)d_in[3];
    const float* enc_w_ih = (const float*)d_in[4];
    const float* enc_w_hh = (const float*)d_in[5];
    const float* enc_b_ih = (const float*)d_in[6];
    const float* enc_b_hh = (const float*)d_in[7];
    const float* dec_w_ih = (const float*)d_in[8];
    const float* dec_w_hh = (const float*)d_in[9];
    const float* dec_b_ih = (const float*)d_in[10];
    const float* dec_b_hh = (const float*)d_in[11];
    const float* head_w   = (const float*)d_in[12];
    const float* t0_proj  = (const float*)d_in[13];
    const float* t0_out   = (const float*)d_in[14];
    const float* t1_proj  = (const float*)d_in[15];
    const float* t1_out   = (const float*)d_in[16];
    float* out = (float*)d_out;

    float *embedded, *inputf, *wgt, *egi, *gi, *gh, *wins, *h, *hs, *z0, *z1;
    float *lh, *l0, *l1;
    __half *hl, *t0l, *t1l;
    float2 *ph, *p0, *p1;
    cudaGetSymbolAddress((void**)&embedded, g_embedded);
    cudaGetSymbolAddress((void**)&inputf,   g_inputf);
    cudaGetSymbolAddress((void**)&wgt,      g_wgt);
    cudaGetSymbolAddress((void**)&egi,      g_egi);
    cudaGetSymbolAddress((void**)&gi,       g_gi);
    cudaGetSymbolAddress((void**)&gh,       g_gh);
    cudaGetSymbolAddress((void**)&wins,     g_wins);
    cudaGetSymbolAddress((void**)&h,        g_h);
    cudaGetSymbolAddress((void**)&hs,       g_hs);
    cudaGetSymbolAddress((void**)&z0,       g_z0);
    cudaGetSymbolAddress((void**)&z1,       g_z1);
    cudaGetSymbolAddress((void**)&hl,       g_headlog);
    cudaGetSymbolAddress((void**)&t0l,      g_t0log);
    cudaGetSymbolAddress((void**)&t1l,      g_t1log);
    cudaGetSymbolAddress((void**)&lh,       g_lseh);
    cudaGetSymbolAddress((void**)&l0,       g_lse0);
    cudaGetSymbolAddress((void**)&l1,       g_lse1);
    cudaGetSymbolAddress((void**)&ph,       g_parth);
    cudaGetSymbolAddress((void**)&p0,       g_part0);
    cudaGetSymbolAddress((void**)&p1,       g_part1);

    static cudaStream_t s2 = 0, s3 = 0, s4 = 0;
    static cudaEvent_t eEmb = 0, eGi = 0, eHs2 = 0, eHs3 = 0;
    static cudaEvent_t eStep[4] = {0, 0, 0, 0};
    static cudaEvent_t eHead2 = 0, eHead3 = 0, eW2 = 0, eW3 = 0, eW4 = 0;
    if (!s2) {
        cudaStreamCreateWithFlags(&s2, cudaStreamNonBlocking);
        cudaStreamCreateWithFlags(&s3, cudaStreamNonBlocking);
        cudaStreamCreateWithFlags(&s4, cudaStreamNonBlocking);
        cudaEventCreateWithFlags(&eEmb,   cudaEventDisableTiming);
        cudaEventCreateWithFlags(&eGi,    cudaEventDisableTiming);
        cudaEventCreateWithFlags(&eHs2,   cudaEventDisableTiming);
        cudaEventCreateWithFlags(&eHs3,   cudaEventDisableTiming);
        for (int d = 0; d < 4; d++) cudaEventCreateWithFlags(&eStep[d], cudaEventDisableTiming);
        cudaEventCreateWithFlags(&eHead2, cudaEventDisableTiming);
        cudaEventCreateWithFlags(&eHead3, cudaEventDisableTiming);
        cudaEventCreateWithFlags(&eW2,    cudaEventDisableTiming);
        cudaEventCreateWithFlags(&eW3,    cudaEventDisableTiming);
        cudaEventCreateWithFlags(&eW4,    cudaEventDisableTiming);
    }

    // 1) embedding (main)
    k_embed<<<NENC, 128>>>(x, emb, embedded, inputf);
    cudaEventRecord(eEmb, 0);

    // side stream s2: window gather + decoder-gi GEMM, concurrent with encoder
    cudaStreamWaitEvent(s2, eEmb, 0);
    k_wingather<<<NROW, 128, 0, s2>>>(embedded, lengths, wins);
    k_tf32_gemm<128, false, false, false><<<dim3(G3H / 128, (NROW + 127) / 128), 256, 0, s2>>>(
        wins, dec_w_ih, gi, 0, 0, 0, NROW, G3H, Ee, G3H, (float2*)0, 0);
    cudaEventRecord(eGi, s2);

    // main: encoder layers (gt einsum: 128-block small-tile version)
    for (int l = 0; l < Ll; l++) {
        k_gt_tf32<<<dim3(Ee / 64, Tt / 32, Bb), 256>>>(G, l, inputf, wgt);
        dim3 gA(G3H / 128, NENC / 32, 2);
        k_tf32_gemm<32, true, false, false><<<gA, 256>>>(
            wgt,    enc_w_ih + (size_t)l * G3H * Hh, egi,
            inputf, enc_w_hh + (size_t)l * G3H * Hh, gh,
            NENC, G3H, Hh, G3H, (float2*)0, 0);
        k_gru_combine<<<(NENC * Hh + 255) / 256, 256>>>(egi, gh, enc_b_ih + l * G3H, enc_b_hh + l * G3H,
                                                        inputf, inputf, NENC, (float*)0, (int*)0, 0);
    }
    k_h0<<<NDEC, 128>>>(inputf, h);

    // join gi
    cudaStreamWaitEvent(0, eGi, 0);

    // decoder: 4 sequential GRU steps; hs step-major chunks; head GEMM chunk per step on s4
    for (int d = 0; d < Dd; d++) {
        k_tf32_gemm<32, false, false, false><<<dim3(G3H / 128, (NDEC + 31) / 32), 256>>>(
            h, dec_w_hh, gh, 0, 0, 0, NDEC, G3H, Hh, G3H, (float2*)0, 0);
        k_gru_combine<<<(NDEC * Hh + 255) / 256, 256>>>(
            gi + (size_t)d * NDEC * G3H, gh, dec_b_ih, dec_b_hh,
            h, h, NDEC, hs + (size_t)d * NDEC * Hh, lengths, d);
        cudaEventRecord(eStep[d], 0);
        // head GEMM chunk for this step's 500 rows (overlaps next decoder step)
        cudaStreamWaitEvent(s4, eStep[d], 0);
        k_tf32_gemm<64, false, true, true><<<dim3(16, (NDEC + 63) / 64), 256, 0, s4>>>(
            hs + (size_t)d * NDEC * Hh, head_w, hl + (size_t)d * NDEC * HLDC,
            0, 0, 0, NDEC, 2002, Hh, HLDC, ph + (size_t)d * NDEC * PH, PH);
    }
    cudaEventRecord(eHs2, 0);
    cudaEventRecord(eHs3, 0);

    // s4: head LSE combine (all chunks done in-order on s4) + head-region write
    k_lse_combine<<<NROW, 128, 0, s4>>>(ph, PH, lh);
    cudaEventRecord(eHead2, s4);
    cudaEventRecord(eHead3, s4);
    k_write_region<<<dim3(2, NROW), 256, 0, s4>>>(hl, HLDC, 0, C0c, hl, 0, lh, (float*)0, lengths, out);
    cudaEventRecord(eW4, s4);

    // s2: t0 chain + t0 write (proj now BM=32: grid (1,63) = 63 blocks)
    cudaStreamWaitEvent(s2, eHs2, 0);
    k_tf32_gemm<32, false, false, false><<<dim3(1, (NROW + 31) / 32), 256, 0, s2>>>(
        hs, t0_proj, z0, 0, 0, 0, NROW, 128, Hh, 128, (float2*)0, 0);
    k_tf32_gemm<128, false, true, true><<<dim3(63, (NROW + 127) / 128), 256, 0, s2>>>(
        z0, t0_out, t0l, 0, 0, 0, NROW, W0, 128, W0, p0, P0);
    k_lse_combine<<<NROW, 128, 0, s2>>>(p0, P0, l0);
    cudaStreamWaitEvent(s2, eHead2, 0);
    k_write_region<<<dim3(8, NROW), 256, 0, s2>>>(t0l, W0, C0c, W0, hl, C0c, lh, l0, lengths, out);
    cudaEventRecord(eW2, s2);

    // s3: t1 chain + t1 write (proj now BM=32)
    cudaStreamWaitEvent(s3, eHs3, 0);
    k_tf32_gemm<32, false, false, false><<<dim3(1, (NROW + 31) / 32), 256, 0, s3>>>(
        hs, t1_proj, z1, 0, 0, 0, NROW, 32, Hh, 32, (float2*)0, 0);
    k_tf32_gemm<128, false, true, true><<<dim3(172, (NROW + 127) / 128), 256, 0, s3>>>(
        z1, t1_out, t1l, 0, 0, 0, NROW, W1, 32, W1, p1, P1);
    k_lse_combine<<<NROW, 128, 0, s3>>>(p1, P1, l1);
    cudaStreamWaitEvent(s3, eHead3, 0);
    k_write_region<<<dim3(22, NROW), 256, 0, s3>>>(t1l, W1, C1c, W1, hl, C0c + 1, lh, l1, lengths, out);
    cudaEventRecord(eW3, s3);

    // join everything back to main
    cudaStreamWaitEvent(0, eW2, 0);
    cudaStreamWaitEvent(0, eW3, 0);
    cudaStreamWaitEvent(0, eW4, 0);
}